// round 12
// baseline (speedup 1.0000x reference)
#include <cuda_runtime.h>
#include <cuda_fp16.h>
#include <cstdint>
#include <cstddef>

#define DIM      1024
#define HEADS    16
#define HEAD_DIM 64
#define BLK      32
#define FEAT     128
#define BATCH    4
#define SEQ      4096
#define NBLK     (SEQ / BLK)      // 128
#define ROWS     (BATCH * SEQ)    // 16384

// Scratch (allocation-free rule: __device__ globals)
__device__ float  g_qkv[(size_t)ROWS * 3 * DIM];     // 192 MB fp32
__device__ __half g_xh[(size_t)ROWS * DIM];
__device__ __half g_ah[(size_t)ROWS * DIM];
__device__ __half g_wqh[(size_t)3 * DIM * DIM];
__device__ __half g_woh[(size_t)DIM * DIM];

// ---------------------------------------------------------------------------
// helpers
// ---------------------------------------------------------------------------
__device__ __forceinline__ uint32_t smem_u32(const void* p) {
    uint32_t a;
    asm("{ .reg .u64 t; cvta.to.shared.u64 t, %1; cvt.u32.u64 %0, t; }" : "=r"(a) : "l"(p));
    return a;
}

#define SW128(off) ((off) ^ (((off) >> 3) & 0x70))

#define CP16(dst, src) \
    asm volatile("cp.async.cg.shared.global [%0], [%1], 16;" :: "r"(dst), "l"(src) : "memory")
#define CP_COMMIT() asm volatile("cp.async.commit_group;" ::: "memory")
#define CP_WAIT1()  asm volatile("cp.async.wait_group 1;" ::: "memory")

#define LDSM4(r0, r1, r2, r3, addr)                                           \
    asm volatile("ldmatrix.sync.aligned.m8n8.x4.shared.b16 {%0,%1,%2,%3}, [%4];" \
                 : "=r"(r0), "=r"(r1), "=r"(r2), "=r"(r3) : "r"(addr))

#define MMA_F16(d, a0, a1, a2, a3, b0, b1)                                    \
    asm volatile("mma.sync.aligned.m16n8k16.row.col.f32.f16.f16.f32 "         \
                 "{%0,%1,%2,%3}, {%4,%5,%6,%7}, {%8,%9}, {%0,%1,%2,%3};"      \
                 : "+f"((d)[0]), "+f"((d)[1]), "+f"((d)[2]), "+f"((d)[3])     \
                 : "r"(a0), "r"(a1), "r"(a2), "r"(a3), "r"(b0), "r"(b1))

// packed f32x2 helpers (Blackwell packed fp32 pipe; 2 MACs per issue)
typedef unsigned long long u64t;

__device__ __forceinline__ u64t pk2(float lo, float hi) {
    u64t r;
    asm("mov.b64 %0, {%1, %2};" : "=l"(r) : "f"(lo), "f"(hi));
    return r;
}
__device__ __forceinline__ float2 upk2(u64t v) {
    float2 f;
    asm("mov.b64 {%0, %1}, %2;" : "=f"(f.x), "=f"(f.y) : "l"(v));
    return f;
}
#define FMA2(d, a, b) \
    asm("fma.rn.f32x2 %0, %1, %2, %0;" : "+l"(d) : "l"(a), "l"(b))

__device__ __forceinline__ float elu1(float x) {
    return (x > 0.0f) ? (x + 1.0f) : __expf(x);
}
__device__ __forceinline__ float f4e(const float4& v, int i) {
    return (i == 0) ? v.x : (i == 1) ? v.y : (i == 2) ? v.z : v.w;
}

// ---------------------------------------------------------------------------
// fp16 mma.sync GEMM (R11 best: at HMMA dispatch wall, 2 CTAs/SM).
// ---------------------------------------------------------------------------
#define BM 128
#define BN 128
#define BKH 64
#define NSTAGE 3
#define TILE_B (BM * 128)
#define ST_BYTES (2 * TILE_B)
#define G_SMEM (NSTAGE * ST_BYTES) // 98304 B

template<bool BIAS>
__global__ __launch_bounds__(256, 2)
void hgemm(const __half* __restrict__ Ah, const __half* __restrict__ Bh,
           const float* __restrict__ bias, float* __restrict__ C,
           int M, int N, int K)
{
    extern __shared__ char smem[];
    const uint32_t sbase = smem_u32(smem);
    const int t = threadIdx.x;
    const int lid = t & 31, wid = t >> 5;
    const int wm = wid & 3, wn = wid >> 2;
    const int m0 = wm * 32, n0 = wn * 64;
    const int bn = blockIdx.x, bm = blockIdx.y;
    const int NK = K / BKH;

    const __half* Ahb = Ah + (size_t)bm * BM * K;
    const __half* Bhb = Bh + (size_t)bn * BN * K;

    const int prow = t >> 3;
    const int pch  = t & 7;

    auto load_stage = [&](int s, int kc) {
        const uint32_t sb0 = sbase + s * ST_BYTES;
        const int koff = kc * BKH;
#pragma unroll
        for (int i = 0; i < 4; i++) {
            int row = prow + i * 32;
            uint32_t off = SW128((uint32_t)(row * 128 + pch * 16));
            size_t g = (size_t)row * K + koff + pch * 8;
            CP16(sb0 + off,          Ahb + g);
            CP16(sb0 + TILE_B + off, Bhb + g);
        }
        CP_COMMIT();
    };

    const int lr = lid & 15;
    const int lk16 = (lid >> 4) * 16;
    const uint32_t aoff = (uint32_t)((m0 + lr) * 128 + lk16);
    uint32_t boff[4];
#pragma unroll
    for (int j = 0; j < 4; j++)
        boff[j] = (uint32_t)((n0 + 16 * j + lr) * 128 + lk16);

    float acc[2][8][4];
#pragma unroll
    for (int mi = 0; mi < 2; mi++)
#pragma unroll
        for (int f = 0; f < 8; f++)
#pragma unroll
            for (int r = 0; r < 4; r++) acc[mi][f][r] = 0.0f;

    load_stage(0, 0);
    load_stage(1, 1);

    for (int it = 0; it < NK; it++) {
        CP_WAIT1();
        __syncthreads();
        const int nxt = it + 2;
        if (nxt < NK) load_stage(nxt % NSTAGE, nxt);

        const uint32_t s0 = sbase + (it % NSTAGE) * ST_BYTES;
        const uint32_t sAh = s0;
        const uint32_t sBh = s0 + TILE_B;

#pragma unroll
        for (int ks = 0; ks < 4; ks++) {
            const uint32_t kb = ks * 32;
            uint32_t ah0[4], ah1[4];
            {
                uint32_t o0 = SW128(aoff + kb);
                uint32_t o1 = SW128(aoff + 16 * 128 + kb);
                LDSM4(ah0[0], ah0[1], ah0[2], ah0[3], sAh + o0);
                LDSM4(ah1[0], ah1[1], ah1[2], ah1[3], sAh + o1);
            }
#pragma unroll
            for (int j = 0; j < 4; j++) {
                uint32_t bh[4];
                uint32_t ob = SW128(boff[j] + kb);
                LDSM4(bh[0], bh[1], bh[2], bh[3], sBh + ob);

                MMA_F16(acc[0][2 * j + 0], ah0[0], ah0[1], ah0[2], ah0[3], bh[0], bh[2]);
                MMA_F16(acc[0][2 * j + 1], ah0[0], ah0[1], ah0[2], ah0[3], bh[1], bh[3]);
                MMA_F16(acc[1][2 * j + 0], ah1[0], ah1[1], ah1[2], ah1[3], bh[0], bh[2]);
                MMA_F16(acc[1][2 * j + 1], ah1[0], ah1[1], ah1[2], ah1[3], bh[1], bh[3]);
            }
        }
    }

    const int g = lid >> 2, tq = lid & 3;
#pragma unroll
    for (int mi = 0; mi < 2; mi++) {
        int rowl = m0 + mi * 16 + g;
#pragma unroll
        for (int f = 0; f < 8; f++) {
            int col = n0 + f * 8 + tq * 2;
            float b0 = 0.0f, b1 = 0.0f;
            if (BIAS) { b0 = bias[bn * BN + col]; b1 = bias[bn * BN + col + 1]; }
            float* p0 = C + (size_t)(bm * BM + rowl) * N + bn * BN + col;
            float* p1 = C + (size_t)(bm * BM + rowl + 8) * N + bn * BN + col;
            float2 v0 = { acc[mi][f][0] + b0, acc[mi][f][1] + b1 };
            float2 v1 = { acc[mi][f][2] + b0, acc[mi][f][3] + b1 };
            *(float2*)p0 = v0;
            *(float2*)p1 = v1;
        }
    }
}

// ---------------------------------------------------------------------------
// Round fp32 -> fp16 (rn), elementwise (float4 vectorized).
// ---------------------------------------------------------------------------
__global__ void round_kernel(const float* __restrict__ in, __half* __restrict__ h,
                             int n4)
{
    int i = blockIdx.x * blockDim.x + threadIdx.x;
    if (i >= n4) return;
    float4 v = ((const float4*)in)[i];
    ((__half2*)h)[2 * i]     = __halves2half2(__float2half_rn(v.x), __float2half_rn(v.y));
    ((__half2*)h)[2 * i + 1] = __halves2half2(__float2half_rn(v.z), __float2half_rn(v.w));
}

// ---------------------------------------------------------------------------
// Transpose + round: in fp32 [R,C] -> out fp16 [C,R] (rn). block (32,8).
// ---------------------------------------------------------------------------
__global__ void transpose_h(const float* __restrict__ in,
                            __half* __restrict__ oh, int R, int C)
{
    __shared__ float tile[32][33];
    int bx = blockIdx.x * 32, by = blockIdx.y * 32;
#pragma unroll
    for (int i = 0; i < 32; i += 8)
        tile[threadIdx.y + i][threadIdx.x] =
            in[(size_t)(by + threadIdx.y + i) * C + bx + threadIdx.x];
    __syncthreads();
#pragma unroll
    for (int i = 0; i < 32; i += 8) {
        size_t idx = (size_t)(bx + threadIdx.y + i) * R + by + threadIdx.x;
        oh[idx] = __float2half_rn(tile[threadIdx.x][threadIdx.y + i]);
    }
}

// ---------------------------------------------------------------------------
// Fused middle with packed f32x2 FMA (2 MACs/issue, numerically identical
// fp32). Phase B: f-pair accumulators + ld.shared.b64 pv pairs. Phase C:
// contiguous (4f x 8d) tile, packed d-pairs, direct u64 stores. Phase D:
// row-pair packing, z folded in (no separate z phase/sync).
// ---------------------------------------------------------------------------
#define SQF_STRIDE 132   // 16B-aligned rows
#define MID_QF    14336
#define MID_KF    (14336 + 32 * SQF_STRIDE)
#define MID_KSUM  (MID_KF + 32 * SQF_STRIDE)
#define MID_SMEM_FLOATS (MID_KSUM + 128)
#define MID_SMEM_BYTES  (MID_SMEM_FLOATS * 4)   // 91648

__global__ __launch_bounds__(256)
void middle_kernel(const float* __restrict__ qkv, const float* __restrict__ proj,
                   __half* __restrict__ attn_h)
{
    extern __shared__ float sm[];
    float* sq    = sm;             // 32x64
    float* sk    = sm + 2048;      // 32x64
    float* sv    = sm + 4096;      // 32x64
    float* sp    = sm + 6144;      // proj 64x128 (aliased as kv[128][64])
    float* skv   = sp;
    float* sqf   = sm + MID_QF;    // 32 x 132
    float* skf   = sm + MID_KF;    // 32 x 132
    float* sksum = sm + MID_KSUM;  // 128

    const int t = threadIdx.x;
    const int gb = blockIdx.x;
    const int b = gb / (HEADS * NBLK);
    const int rem = gb - b * (HEADS * NBLK);
    const int h = rem / NBLK;
    const int m = rem - h * NBLK;

    // ---- phase A: stage q/k/v and proj ----
    const float* base = qkv + ((size_t)(b * SEQ + m * BLK)) * (3 * DIM) + h * HEAD_DIM;
    for (int v4 = t; v4 < 512; v4 += 256) {
        int s = v4 >> 4, c = v4 & 15;
        const float* r = base + (size_t)s * (3 * DIM) + c * 4;
        ((float4*)sq)[v4] = *(const float4*)(r);
        ((float4*)sk)[v4] = *(const float4*)(r + DIM);
        ((float4*)sv)[v4] = *(const float4*)(r + 2 * DIM);
    }
    const float* ph = proj + (size_t)h * HEAD_DIM * FEAT;
    for (int v4 = t; v4 < 2048; v4 += 256)
        ((float4*)sp)[v4] = ((const float4*)ph)[v4];
    __syncthreads();

    // ---- phase B: qf/kf = elu(x @ proj)+1; f-pairs {2tF,2tF+1},{64+2tF,..} ----
    {
        const int tS = t >> 5;
        const int tF = t & 31;
        u64t qa2[4][2], ka2[4][2];
#pragma unroll
        for (int i = 0; i < 4; i++) {
            qa2[i][0] = 0; qa2[i][1] = 0;
            ka2[i][0] = 0; ka2[i][1] = 0;
        }

        for (int d4 = 0; d4 < HEAD_DIM; d4 += 4) {
            float4 q4[4], k4[4];
#pragma unroll
            for (int i = 0; i < 4; i++) {
                q4[i] = *(const float4*)&sq[(tS + 8 * i) * 64 + d4];
                k4[i] = *(const float4*)&sk[(tS + 8 * i) * 64 + d4];
            }
#pragma unroll
            for (int dd = 0; dd < 4; dd++) {
                const float* pr = sp + (d4 + dd) * 128;
                u64t pv0 = *(const u64t*)(pr + 2 * tF);
                u64t pv1 = *(const u64t*)(pr + 64 + 2 * tF);
#pragma unroll
                for (int i = 0; i < 4; i++) {
                    float qd = f4e(q4[i], dd);
                    float kd = f4e(k4[i], dd);
                    u64t q2 = pk2(qd, qd);
                    u64t k2 = pk2(kd, kd);
                    FMA2(qa2[i][0], q2, pv0);
                    FMA2(qa2[i][1], q2, pv1);
                    FMA2(ka2[i][0], k2, pv0);
                    FMA2(ka2[i][1], k2, pv1);
                }
            }
        }
#pragma unroll
        for (int i = 0; i < 4; i++) {
            int s = tS + 8 * i;
#pragma unroll
            for (int p = 0; p < 2; p++) {
                int f = (p == 0) ? (2 * tF) : (64 + 2 * tF);
                float2 q = upk2(qa2[i][p]);
                float2 k = upk2(ka2[i][p]);
                float2 qe = { elu1(q.x), elu1(q.y) };
                float2 ke = { elu1(k.x), elu1(k.y) };
                *(float2*)&sqf[s * SQF_STRIDE + f] = qe;
                *(float2*)&skf[s * SQF_STRIDE + f] = ke;
            }
        }
    }
    __syncthreads();

    // ---- phase C: kv[f][d] = sum_s kf[s][f]*v[s][d]; ksum ----
    {
        const int cf = (t >> 3) * 4;   // 4 consecutive f
        const int cd = (t & 7) * 8;    // 8 consecutive d
        u64t kva2[4][4];
#pragma unroll
        for (int j = 0; j < 4; j++)
#pragma unroll
            for (int i = 0; i < 4; i++) kva2[j][i] = 0;

        for (int s = 0; s < BLK; s++) {
            float4 kf4 = *(const float4*)&skf[s * SQF_STRIDE + cf];
            float4 va  = *(const float4*)&sv[s * 64 + cd];
            float4 vb  = *(const float4*)&sv[s * 64 + cd + 4];
            u64t v0 = pk2(va.x, va.y), v1 = pk2(va.z, va.w);
            u64t v2 = pk2(vb.x, vb.y), v3 = pk2(vb.z, vb.w);
            float kf[4] = { kf4.x, kf4.y, kf4.z, kf4.w };
#pragma unroll
            for (int j = 0; j < 4; j++) {
                u64t kj = pk2(kf[j], kf[j]);
                FMA2(kva2[j][0], kj, v0);
                FMA2(kva2[j][1], kj, v1);
                FMA2(kva2[j][2], kj, v2);
                FMA2(kva2[j][3], kj, v3);
            }
        }
        if (t < FEAT) {
            float acc = 0.0f;
            for (int s = 0; s < BLK; s++) acc += skf[s * SQF_STRIDE + t];
            sksum[t] = acc;
        }
#pragma unroll
        for (int j = 0; j < 4; j++) {
            u64t* dst = (u64t*)&skv[(cf + j) * 64 + cd];
            dst[0] = kva2[j][0]; dst[1] = kva2[j][1];
            dst[2] = kva2[j][2]; dst[3] = kva2[j][3];
        }
    }
    __syncthreads();

    // ---- phase D: out[s][d] = z[s] * sum_f qf[s][f]*kv[f][d]; z folded ----
    {
        const int tS = t >> 5;
        const int lane = t & 31;
        u64t oa2[2][2] = { {0, 0}, {0, 0} };  // [row-pair p][col-group c]
        u64t za2[2] = { 0, 0 };               // z dot-products, row-paired

        for (int f4 = 0; f4 < FEAT; f4 += 4) {
            float4 qf4[4];
#pragma unroll
            for (int i = 0; i < 4; i++)
                qf4[i] = *(const float4*)&sqf[(tS + 8 * i) * SQF_STRIDE + f4];
            float4 ks4 = *(const float4*)&sksum[f4];
#pragma unroll
            for (int ff = 0; ff < 4; ff++) {
                float kv0 = skv[(f4 + ff) * 64 + lane];
                float kv1 = skv[(f4 + ff) * 64 + lane + 32];
                u64t kv0s = pk2(kv0, kv0);
                u64t kv1s = pk2(kv1, kv1);
                float ks = f4e(ks4, ff);
                u64t kss = pk2(ks, ks);
#pragma unroll
                for (int p = 0; p < 2; p++) {
                    u64t a2 = pk2(f4e(qf4[2 * p], ff), f4e(qf4[2 * p + 1], ff));
                    FMA2(oa2[p][0], a2, kv0s);
                    FMA2(oa2[p][1], a2, kv1s);
                    FMA2(za2[p], a2, kss);
                }
            }
        }
        const int rowbase = b * SEQ + m * BLK;
#pragma unroll
        for (int p = 0; p < 2; p++) {
            float2 zz = upk2(za2[p]);
            float2 o0 = upk2(oa2[p][0]);
            float2 o1 = upk2(oa2[p][1]);
            {
                int s = tS + 8 * (2 * p);
                float z = 1.0f / (zz.x + 1e-8f);
                size_t off = (size_t)(rowbase + s) * DIM + h * HEAD_DIM;
                attn_h[off + lane]      = __float2half_rn(o0.x * z);
                attn_h[off + lane + 32] = __float2half_rn(o1.x * z);
            }
            {
                int s = tS + 8 * (2 * p + 1);
                float z = 1.0f / (zz.y + 1e-8f);
                size_t off = (size_t)(rowbase + s) * DIM + h * HEAD_DIM;
                attn_h[off + lane]      = __float2half_rn(o0.y * z);
                attn_h[off + lane + 32] = __float2half_rn(o1.y * z);
            }
        }
    }
}

// ---------------------------------------------------------------------------
extern "C" void kernel_launch(void* const* d_in, const int* in_sizes, int n_in,
                              void* d_out, int out_size)
{
    const float* x    = (const float*)d_in[0];
    const float* Wqkv = (const float*)d_in[1];
    const float* proj = (const float*)d_in[2];
    const float* Wout = (const float*)d_in[3];
    const float* bout = (const float*)d_in[4];
    float* out = (float*)d_out;

    float*  qkv; cudaGetSymbolAddress((void**)&qkv, g_qkv);
    __half *xh, *ah, *wqh, *woh;
    cudaGetSymbolAddress((void**)&xh,  g_xh);
    cudaGetSymbolAddress((void**)&ah,  g_ah);
    cudaGetSymbolAddress((void**)&wqh, g_wqh);
    cudaGetSymbolAddress((void**)&woh, g_woh);

    cudaFuncSetAttribute(middle_kernel, cudaFuncAttributeMaxDynamicSharedMemorySize,
                         MID_SMEM_BYTES);
    cudaFuncSetAttribute(hgemm<false>, cudaFuncAttributeMaxDynamicSharedMemorySize,
                         G_SMEM);
    cudaFuncSetAttribute(hgemm<true>, cudaFuncAttributeMaxDynamicSharedMemorySize,
                         G_SMEM);

    // 0) operand prep: round x; transpose+round weights
    {
        int n4 = ROWS * DIM / 4;
        round_kernel<<<(n4 + 255) / 256, 256>>>(x, xh, n4);
    }
    transpose_h<<<dim3((3 * DIM) / 32, DIM / 32), dim3(32, 8)>>>(Wqkv, wqh, DIM, 3 * DIM);
    transpose_h<<<dim3(DIM / 32, DIM / 32), dim3(32, 8)>>>(Wout, woh, DIM, DIM);

    // 1) qkv = x @ Wqkv  (fp16 mma.sync, fp32 accumulate)
    hgemm<false><<<dim3((3 * DIM) / BN, ROWS / BM), 256, G_SMEM>>>(
        xh, wqh, nullptr, qkv, ROWS, 3 * DIM, DIM);

    // 2) fused per-block linear attention (packed f32x2 math, fp16 out)
    middle_kernel<<<BATCH * HEADS * NBLK, 256, MID_SMEM_BYTES>>>(qkv, proj, ah);

    // 3) out = attn @ Wout + bout  (fp16 mma.sync)
    hgemm<true><<<dim3(DIM / BN, ROWS / BM), 256, G_SMEM>>>(
        ah, woh, bout, out, ROWS, DIM, DIM);
}

// round 13
// speedup vs baseline: 1.1490x; 1.1490x over previous
#include <cuda_runtime.h>
#include <cuda_fp16.h>
#include <cstdint>
#include <cstddef>

#define DIM      1024
#define HEADS    16
#define HEAD_DIM 64
#define BLK      32
#define FEAT     128
#define BATCH    4
#define SEQ      4096
#define NBLK     (SEQ / BLK)      // 128
#define ROWS     (BATCH * SEQ)    // 16384

// Scratch (allocation-free rule: __device__ globals)
__device__ float  g_qkv[(size_t)ROWS * 3 * DIM];             // 192 MB fp32
__device__ __half g_xh[(size_t)ROWS * DIM];                  // 32 MB
__device__ __half g_ah[(size_t)ROWS * DIM];                  // 32 MB
__device__ __half g_wqh[(size_t)3 * DIM * DIM];              // 6 MB
__device__ __half g_woh[(size_t)DIM * DIM];                  // 2 MB
__device__ __half g_pt[(size_t)HEADS * FEAT * HEAD_DIM];     // 256 KB projT [h][f][d]
__device__ __half g_qf[(size_t)BATCH * HEADS * SEQ * FEAT];  // 64 MB [b,h][n][f]
__device__ __half g_kf[(size_t)BATCH * HEADS * SEQ * FEAT];  // 64 MB

// ---------------------------------------------------------------------------
// helpers
// ---------------------------------------------------------------------------
__device__ __forceinline__ uint32_t smem_u32(const void* p) {
    uint32_t a;
    asm("{ .reg .u64 t; cvta.to.shared.u64 t, %1; cvt.u32.u64 %0, t; }" : "=r"(a) : "l"(p));
    return a;
}

#define SW128(off) ((off) ^ (((off) >> 3) & 0x70))

#define CP16(dst, src) \
    asm volatile("cp.async.cg.shared.global [%0], [%1], 16;" :: "r"(dst), "l"(src) : "memory")
#define CP_COMMIT() asm volatile("cp.async.commit_group;" ::: "memory")
#define CP_WAIT1()  asm volatile("cp.async.wait_group 1;" ::: "memory")
#define CP_WAIT0()  asm volatile("cp.async.wait_group 0;" ::: "memory")

#define LDSM4(r0, r1, r2, r3, addr)                                           \
    asm volatile("ldmatrix.sync.aligned.m8n8.x4.shared.b16 {%0,%1,%2,%3}, [%4];" \
                 : "=r"(r0), "=r"(r1), "=r"(r2), "=r"(r3) : "r"(addr))

#define MMA_F16(d, a0, a1, a2, a3, b0, b1)                                    \
    asm volatile("mma.sync.aligned.m16n8k16.row.col.f32.f16.f16.f32 "         \
                 "{%0,%1,%2,%3}, {%4,%5,%6,%7}, {%8,%9}, {%0,%1,%2,%3};"      \
                 : "+f"((d)[0]), "+f"((d)[1]), "+f"((d)[2]), "+f"((d)[3])     \
                 : "r"(a0), "r"(a1), "r"(a2), "r"(a3), "r"(b0), "r"(b1))

__device__ __forceinline__ float elu1(float x) {
    return (x > 0.0f) ? (x + 1.0f) : __expf(x);
}

// ---------------------------------------------------------------------------
// fp16 mma.sync GEMM (R11 best: at HMMA dispatch wall, 2 CTAs/SM).
// ---------------------------------------------------------------------------
#define BM 128
#define BN 128
#define BKH 64
#define NSTAGE 3
#define TILE_B (BM * 128)
#define ST_BYTES (2 * TILE_B)
#define G_SMEM (NSTAGE * ST_BYTES) // 98304 B

template<bool BIAS>
__global__ __launch_bounds__(256, 2)
void hgemm(const __half* __restrict__ Ah, const __half* __restrict__ Bh,
           const float* __restrict__ bias, float* __restrict__ C,
           int M, int N, int K)
{
    extern __shared__ char smem[];
    const uint32_t sbase = smem_u32(smem);
    const int t = threadIdx.x;
    const int lid = t & 31, wid = t >> 5;
    const int wm = wid & 3, wn = wid >> 2;
    const int m0 = wm * 32, n0 = wn * 64;
    const int bn = blockIdx.x, bm = blockIdx.y;
    const int NK = K / BKH;

    const __half* Ahb = Ah + (size_t)bm * BM * K;
    const __half* Bhb = Bh + (size_t)bn * BN * K;

    const int prow = t >> 3;
    const int pch  = t & 7;

    auto load_stage = [&](int s, int kc) {
        const uint32_t sb0 = sbase + s * ST_BYTES;
        const int koff = kc * BKH;
#pragma unroll
        for (int i = 0; i < 4; i++) {
            int row = prow + i * 32;
            uint32_t off = SW128((uint32_t)(row * 128 + pch * 16));
            size_t g = (size_t)row * K + koff + pch * 8;
            CP16(sb0 + off,          Ahb + g);
            CP16(sb0 + TILE_B + off, Bhb + g);
        }
        CP_COMMIT();
    };

    const int lr = lid & 15;
    const int lk16 = (lid >> 4) * 16;
    const uint32_t aoff = (uint32_t)((m0 + lr) * 128 + lk16);
    uint32_t boff[4];
#pragma unroll
    for (int j = 0; j < 4; j++)
        boff[j] = (uint32_t)((n0 + 16 * j + lr) * 128 + lk16);

    float acc[2][8][4];
#pragma unroll
    for (int mi = 0; mi < 2; mi++)
#pragma unroll
        for (int f = 0; f < 8; f++)
#pragma unroll
            for (int r = 0; r < 4; r++) acc[mi][f][r] = 0.0f;

    load_stage(0, 0);
    load_stage(1, 1);

    for (int it = 0; it < NK; it++) {
        CP_WAIT1();
        __syncthreads();
        const int nxt = it + 2;
        if (nxt < NK) load_stage(nxt % NSTAGE, nxt);

        const uint32_t s0 = sbase + (it % NSTAGE) * ST_BYTES;
        const uint32_t sAh = s0;
        const uint32_t sBh = s0 + TILE_B;

#pragma unroll
        for (int ks = 0; ks < 4; ks++) {
            const uint32_t kb = ks * 32;
            uint32_t ah0[4], ah1[4];
            {
                uint32_t o0 = SW128(aoff + kb);
                uint32_t o1 = SW128(aoff + 16 * 128 + kb);
                LDSM4(ah0[0], ah0[1], ah0[2], ah0[3], sAh + o0);
                LDSM4(ah1[0], ah1[1], ah1[2], ah1[3], sAh + o1);
            }
#pragma unroll
            for (int j = 0; j < 4; j++) {
                uint32_t bh[4];
                uint32_t ob = SW128(boff[j] + kb);
                LDSM4(bh[0], bh[1], bh[2], bh[3], sBh + ob);

                MMA_F16(acc[0][2 * j + 0], ah0[0], ah0[1], ah0[2], ah0[3], bh[0], bh[2]);
                MMA_F16(acc[0][2 * j + 1], ah0[0], ah0[1], ah0[2], ah0[3], bh[1], bh[3]);
                MMA_F16(acc[1][2 * j + 0], ah1[0], ah1[1], ah1[2], ah1[3], bh[0], bh[2]);
                MMA_F16(acc[1][2 * j + 1], ah1[0], ah1[1], ah1[2], ah1[3], bh[1], bh[3]);
            }
        }
    }

    const int g = lid >> 2, tq = lid & 3;
#pragma unroll
    for (int mi = 0; mi < 2; mi++) {
        int rowl = m0 + mi * 16 + g;
#pragma unroll
        for (int f = 0; f < 8; f++) {
            int col = n0 + f * 8 + tq * 2;
            float b0 = 0.0f, b1 = 0.0f;
            if (BIAS) { b0 = bias[bn * BN + col]; b1 = bias[bn * BN + col + 1]; }
            float* p0 = C + (size_t)(bm * BM + rowl) * N + bn * BN + col;
            float* p1 = C + (size_t)(bm * BM + rowl + 8) * N + bn * BN + col;
            float2 v0 = { acc[mi][f][0] + b0, acc[mi][f][1] + b1 };
            float2 v1 = { acc[mi][f][2] + b0, acc[mi][f][3] + b1 };
            *(float2*)p0 = v0;
            *(float2*)p1 = v1;
        }
    }
}

// ---------------------------------------------------------------------------
// feat_gemm: qf/kf = elu([128 tokens, 64] @ projT_h^T) + 1 via HMMA.
// A = q (or k) slice of qkv (fp32 -> fp16 staged, SW128); B = projT_h fp16.
// One CTA per (b*h, 128-token tile). K=64 single-shot, N=128.
// ---------------------------------------------------------------------------
#define FT_SMEM (3 * 16384)   // q tile + k tile + B tile

__global__ __launch_bounds__(256)
void feat_gemm(const float* __restrict__ qkv, const __half* __restrict__ pt,
               __half* __restrict__ qf, __half* __restrict__ kf)
{
    extern __shared__ char smem[];
    const uint32_t sbase = smem_u32(smem);
    const uint32_t sQ = sbase, sK = sbase + 16384, sB = sbase + 32768;
    const int t = threadIdx.x;
    const int lid = t & 31, wid = t >> 5;
    const int wm = wid & 3, wn = wid >> 2;
    const int m0 = wm * 32, n0 = wn * 64;
    const int bh = blockIdx.x;           // b*HEADS + h
    const int nt = blockIdx.y;           // 128-token tile
    const int b = bh / HEADS, h = bh - b * HEADS;
    const size_t rowbase = (size_t)b * SEQ + nt * 128;

    // ---- stage B (projT_h, fp16, 128 rows x 128B) via cp.async ----
    {
        const __half* src = pt + (size_t)h * FEAT * HEAD_DIM;
        int r = t >> 1, half = (t & 1) * 64;
#pragma unroll
        for (int c = 0; c < 4; c++) {
            uint32_t off = SW128((uint32_t)(r * 128 + half + c * 16));
            CP16(sB + off, src + r * 64 + (half + c * 16) / 2);
        }
        CP_COMMIT();
    }
    // ---- stage q,k: fp32 global -> fp16 swizzled smem ----
    {
        int r = t >> 1, half = t & 1;    // 32 floats per (r, half)
        const float* qrow = qkv + (rowbase + r) * (3 * DIM) + h * HEAD_DIM + half * 32;
        const float* krow = qrow + DIM;
#pragma unroll
        for (int c = 0; c < 4; c++) {
            float4 a = *(const float4*)(qrow + c * 8);
            float4 d = *(const float4*)(qrow + c * 8 + 4);
            __half2 h0 = __floats2half2_rn(a.x, a.y), h1 = __floats2half2_rn(a.z, a.w);
            __half2 h2 = __floats2half2_rn(d.x, d.y), h3 = __floats2half2_rn(d.z, d.w);
            uint4 v = { *(uint32_t*)&h0, *(uint32_t*)&h1, *(uint32_t*)&h2, *(uint32_t*)&h3 };
            uint32_t off = SW128((uint32_t)(r * 128 + half * 64 + c * 16));
            *(uint4*)(smem + 0 + off) = v;           // q region at offset 0

            a = *(const float4*)(krow + c * 8);
            d = *(const float4*)(krow + c * 8 + 4);
            h0 = __floats2half2_rn(a.x, a.y); h1 = __floats2half2_rn(a.z, a.w);
            h2 = __floats2half2_rn(d.x, d.y); h3 = __floats2half2_rn(d.z, d.w);
            uint4 w = { *(uint32_t*)&h0, *(uint32_t*)&h1, *(uint32_t*)&h2, *(uint32_t*)&h3 };
            *(uint4*)(smem + 16384 + off) = w;       // k region
        }
    }
    CP_WAIT0();
    __syncthreads();

    const int lr = lid & 15;
    const int lk16 = (lid >> 4) * 16;
    const uint32_t aoff = (uint32_t)((m0 + lr) * 128 + lk16);
    uint32_t boff[4];
#pragma unroll
    for (int j = 0; j < 4; j++)
        boff[j] = (uint32_t)((n0 + 16 * j + lr) * 128 + lk16);

    const int g = lid >> 2, tq = lid & 3;

#pragma unroll
    for (int op = 0; op < 2; op++) {
        const uint32_t sA = op ? sK : sQ;
        float acc[2][8][4];
#pragma unroll
        for (int mi = 0; mi < 2; mi++)
#pragma unroll
            for (int f = 0; f < 8; f++)
#pragma unroll
                for (int r = 0; r < 4; r++) acc[mi][f][r] = 0.0f;

#pragma unroll
        for (int ks = 0; ks < 4; ks++) {
            const uint32_t kb = ks * 32;
            uint32_t a0[4], a1[4];
            LDSM4(a0[0], a0[1], a0[2], a0[3], sA + SW128(aoff + kb));
            LDSM4(a1[0], a1[1], a1[2], a1[3], sA + SW128(aoff + 16 * 128 + kb));
#pragma unroll
            for (int j = 0; j < 4; j++) {
                uint32_t bfr[4];
                LDSM4(bfr[0], bfr[1], bfr[2], bfr[3], sB + SW128(boff[j] + kb));
                MMA_F16(acc[0][2 * j + 0], a0[0], a0[1], a0[2], a0[3], bfr[0], bfr[2]);
                MMA_F16(acc[0][2 * j + 1], a0[0], a0[1], a0[2], a0[3], bfr[1], bfr[3]);
                MMA_F16(acc[1][2 * j + 0], a1[0], a1[1], a1[2], a1[3], bfr[0], bfr[2]);
                MMA_F16(acc[1][2 * j + 1], a1[0], a1[1], a1[2], a1[3], bfr[1], bfr[3]);
            }
        }

        __half* dst = (op ? kf : qf) + ((size_t)bh * SEQ + nt * 128) * FEAT;
#pragma unroll
        for (int mi = 0; mi < 2; mi++) {
            int rowl = m0 + mi * 16 + g;
#pragma unroll
            for (int f = 0; f < 8; f++) {
                int col = n0 + f * 8 + tq * 2;
                __half2 v0 = __floats2half2_rn(elu1(acc[mi][f][0]), elu1(acc[mi][f][1]));
                __half2 v1 = __floats2half2_rn(elu1(acc[mi][f][2]), elu1(acc[mi][f][3]));
                *(__half2*)(dst + (size_t)rowl * FEAT + col)       = v0;
                *(__half2*)(dst + (size_t)(rowl + 8) * FEAT + col) = v1;
            }
        }
    }
}

// ---------------------------------------------------------------------------
// Round fp32 -> fp16 (rn), elementwise (float4 vectorized).
// ---------------------------------------------------------------------------
__global__ void round_kernel(const float* __restrict__ in, __half* __restrict__ h,
                             int n4)
{
    int i = blockIdx.x * blockDim.x + threadIdx.x;
    if (i >= n4) return;
    float4 v = ((const float4*)in)[i];
    ((__half2*)h)[2 * i]     = __halves2half2(__float2half_rn(v.x), __float2half_rn(v.y));
    ((__half2*)h)[2 * i + 1] = __halves2half2(__float2half_rn(v.z), __float2half_rn(v.w));
}

// ---------------------------------------------------------------------------
// Transpose + round: in fp32 [R,C] -> out fp16 [C,R] (rn). block (32,8).
// ---------------------------------------------------------------------------
__global__ void transpose_h(const float* __restrict__ in,
                            __half* __restrict__ oh, int R, int C)
{
    __shared__ float tile[32][33];
    int bx = blockIdx.x * 32, by = blockIdx.y * 32;
#pragma unroll
    for (int i = 0; i < 32; i += 8)
        tile[threadIdx.y + i][threadIdx.x] =
            in[(size_t)(by + threadIdx.y + i) * C + bx + threadIdx.x];
    __syncthreads();
#pragma unroll
    for (int i = 0; i < 32; i += 8) {
        size_t idx = (size_t)(bx + threadIdx.y + i) * R + by + threadIdx.x;
        oh[idx] = __float2half_rn(tile[threadIdx.x][threadIdx.y + i]);
    }
}

// ---------------------------------------------------------------------------
// Transpose proj per head: proj [16][64][128] -> projT fp16 [16][128][64].
// grid (4, 2, 16), block (32,8).
// ---------------------------------------------------------------------------
__global__ void transpose_ph(const float* __restrict__ in, __half* __restrict__ out)
{
    __shared__ float tile[32][33];
    int hh = blockIdx.z;
    int bx = blockIdx.x * 32;   // f
    int by = blockIdx.y * 32;   // d
    const float* src = in + (size_t)hh * HEAD_DIM * FEAT;
    __half* dst = out + (size_t)hh * FEAT * HEAD_DIM;
#pragma unroll
    for (int i = 0; i < 32; i += 8)
        tile[threadIdx.y + i][threadIdx.x] =
            src[(size_t)(by + threadIdx.y + i) * FEAT + bx + threadIdx.x];
    __syncthreads();
#pragma unroll
    for (int i = 0; i < 32; i += 8)
        dst[(size_t)(bx + threadIdx.y + i) * HEAD_DIM + by + threadIdx.x] =
            __float2half_rn(tile[threadIdx.x][threadIdx.y + i]);
}

// ---------------------------------------------------------------------------
// middle2: per (b,h,m) block: kv = kf^T @ v, z, out = (qf @ kv) * z.
// qf/kf come from feat_gemm (fp16, converted to fp32 in smem). 75.4KB smem.
// ---------------------------------------------------------------------------
#define M2_STRIDE 132
#define M2_V     0                         // 32x64 = 2048
#define M2_KV    2048                      // 128x64 = 8192
#define M2_QF    10240                     // 32x132 = 4224
#define M2_KF    (10240 + 32 * M2_STRIDE)  // 14464
#define M2_KSUM  (M2_KF + 32 * M2_STRIDE)  // 18688
#define M2_Z     (M2_KSUM + 128)           // 18816
#define M2_SMEM_FLOATS (M2_Z + 32)         // 18848
#define M2_SMEM_BYTES  (M2_SMEM_FLOATS * 4) // 75392

__global__ __launch_bounds__(256)
void middle2(const float* __restrict__ qkv,
             const __half* __restrict__ qf, const __half* __restrict__ kf,
             __half* __restrict__ attn_h)
{
    extern __shared__ float sm[];
    float* sv    = sm + M2_V;
    float* skv   = sm + M2_KV;
    float* sqf   = sm + M2_QF;
    float* skf   = sm + M2_KF;
    float* sksum = sm + M2_KSUM;
    float* sz    = sm + M2_Z;

    const int t = threadIdx.x;
    const int gb = blockIdx.x;
    const int b = gb / (HEADS * NBLK);
    const int rem = gb - b * (HEADS * NBLK);
    const int h = rem / NBLK;
    const int m = rem - h * NBLK;

    // ---- stage v (fp32) and qf/kf (fp16 -> fp32) ----
    const float* vbase = qkv + ((size_t)(b * SEQ + m * BLK)) * (3 * DIM)
                       + 2 * DIM + h * HEAD_DIM;
    for (int v4 = t; v4 < 512; v4 += 256) {
        int s = v4 >> 4, c = v4 & 15;
        ((float4*)sv)[v4] = *(const float4*)(vbase + (size_t)s * (3 * DIM) + c * 4);
    }
    const __half* qsrc = qf + ((size_t)(b * HEADS + h) * SEQ + m * BLK) * FEAT;
    const __half* ksrc = kf + ((size_t)(b * HEADS + h) * SEQ + m * BLK) * FEAT;
    for (int idx = t; idx < 512; idx += 256) {
        int row = idx >> 4, g8 = idx & 15;     // 8 fp16 per slot
        int f0 = g8 * 8;
        uint4 qv = *(const uint4*)(qsrc + (size_t)row * FEAT + f0);
        uint4 kv = *(const uint4*)(ksrc + (size_t)row * FEAT + f0);
        const __half2* qh = (const __half2*)&qv;
        const __half2* kh = (const __half2*)&kv;
        float* qd = sqf + row * M2_STRIDE + f0;
        float* kd = skf + row * M2_STRIDE + f0;
#pragma unroll
        for (int p = 0; p < 4; p++) {
            float2 qq = __half22float2(qh[p]);
            float2 kk = __half22float2(kh[p]);
            qd[2 * p] = qq.x; qd[2 * p + 1] = qq.y;
            kd[2 * p] = kk.x; kd[2 * p + 1] = kk.y;
        }
    }
    __syncthreads();

    // ---- phase C: kv[f][d] = sum_s kf[s][f] * v[s][d] ; ksum ----
    {
        const int tF = t >> 3;
        const int tD = t & 7;
        float kva[4][8];
#pragma unroll
        for (int j = 0; j < 4; j++)
#pragma unroll
            for (int i = 0; i < 8; i++) kva[j][i] = 0.0f;

        for (int s = 0; s < BLK; s++) {
            float kfv[4], vv[8];
#pragma unroll
            for (int j = 0; j < 4; j++) kfv[j] = skf[s * M2_STRIDE + tF + 32 * j];
#pragma unroll
            for (int i = 0; i < 8; i++) vv[i] = sv[s * 64 + tD + 8 * i];
#pragma unroll
            for (int j = 0; j < 4; j++)
#pragma unroll
                for (int i = 0; i < 8; i++)
                    kva[j][i] += kfv[j] * vv[i];
        }
        if (t < FEAT) {
            float acc = 0.0f;
            for (int s = 0; s < BLK; s++) acc += skf[s * M2_STRIDE + t];
            sksum[t] = acc;
        }
#pragma unroll
        for (int j = 0; j < 4; j++)
#pragma unroll
            for (int i = 0; i < 8; i++)
                skv[(tF + 32 * j) * 64 + tD + 8 * i] = kva[j][i];
    }
    __syncthreads();

    if (t < BLK) {
        float acc = 0.0f;
        for (int f = 0; f < FEAT; f++) acc += sqf[t * M2_STRIDE + f] * sksum[f];
        sz[t] = 1.0f / (acc + 1e-8f);
    }
    __syncthreads();

    // ---- phase D: out[s][d] = z[s] * sum_f qf[s][f] * kv[f][d] ----
    {
        const int tS = t >> 5;
        const int lane = t & 31;
        float oa[4][2];
#pragma unroll
        for (int i = 0; i < 4; i++) { oa[i][0] = 0.0f; oa[i][1] = 0.0f; }

        for (int f = 0; f < FEAT; f++) {
            float qv[4], kvv[2];
#pragma unroll
            for (int i = 0; i < 4; i++) qv[i] = sqf[(tS + 8 * i) * M2_STRIDE + f];
            kvv[0] = skv[f * 64 + lane];
            kvv[1] = skv[f * 64 + lane + 32];
#pragma unroll
            for (int i = 0; i < 4; i++) {
                oa[i][0] += qv[i] * kvv[0];
                oa[i][1] += qv[i] * kvv[1];
            }
        }
        const int rowbase = b * SEQ + m * BLK;
#pragma unroll
        for (int i = 0; i < 4; i++) {
            int s = tS + 8 * i;
            float zz = sz[s];
            size_t off = (size_t)(rowbase + s) * DIM + h * HEAD_DIM;
            attn_h[off + lane]      = __float2half_rn(oa[i][0] * zz);
            attn_h[off + lane + 32] = __float2half_rn(oa[i][1] * zz);
        }
    }
}

// ---------------------------------------------------------------------------
extern "C" void kernel_launch(void* const* d_in, const int* in_sizes, int n_in,
                              void* d_out, int out_size)
{
    const float* x    = (const float*)d_in[0];
    const float* Wqkv = (const float*)d_in[1];
    const float* proj = (const float*)d_in[2];
    const float* Wout = (const float*)d_in[3];
    const float* bout = (const float*)d_in[4];
    float* out = (float*)d_out;

    float*  qkv; cudaGetSymbolAddress((void**)&qkv, g_qkv);
    __half *xh, *ah, *wqh, *woh, *pt, *qfp, *kfp;
    cudaGetSymbolAddress((void**)&xh,  g_xh);
    cudaGetSymbolAddress((void**)&ah,  g_ah);
    cudaGetSymbolAddress((void**)&wqh, g_wqh);
    cudaGetSymbolAddress((void**)&woh, g_woh);
    cudaGetSymbolAddress((void**)&pt,  g_pt);
    cudaGetSymbolAddress((void**)&qfp, g_qf);
    cudaGetSymbolAddress((void**)&kfp, g_kf);

    cudaFuncSetAttribute(hgemm<false>, cudaFuncAttributeMaxDynamicSharedMemorySize, G_SMEM);
    cudaFuncSetAttribute(hgemm<true>,  cudaFuncAttributeMaxDynamicSharedMemorySize, G_SMEM);
    cudaFuncSetAttribute(feat_gemm,    cudaFuncAttributeMaxDynamicSharedMemorySize, FT_SMEM);
    cudaFuncSetAttribute(middle2,      cudaFuncAttributeMaxDynamicSharedMemorySize, M2_SMEM_BYTES);

    // 0) operand prep
    {
        int n4 = ROWS * DIM / 4;
        round_kernel<<<(n4 + 255) / 256, 256>>>(x, xh, n4);
    }
    transpose_h<<<dim3((3 * DIM) / 32, DIM / 32), dim3(32, 8)>>>(Wqkv, wqh, DIM, 3 * DIM);
    transpose_h<<<dim3(DIM / 32, DIM / 32), dim3(32, 8)>>>(Wout, woh, DIM, DIM);
    transpose_ph<<<dim3(FEAT / 32, HEAD_DIM / 32, HEADS), dim3(32, 8)>>>(proj, pt);

    // 1) qkv = x @ Wqkv  (fp16 mma.sync)
    hgemm<false><<<dim3((3 * DIM) / BN, ROWS / BM), 256, G_SMEM>>>(
        xh, wqh, nullptr, qkv, ROWS, 3 * DIM, DIM);

    // 2a) qf/kf = elu(q/k @ proj_h)+1 for all tokens (HMMA)
    feat_gemm<<<dim3(BATCH * HEADS, SEQ / 128), 256, FT_SMEM>>>(qkv, pt, qfp, kfp);

    // 2b) per-block kv/z/out
    middle2<<<BATCH * HEADS * NBLK, 256, M2_SMEM_BYTES>>>(qkv, qfp, kfp, ah);

    // 3) out = attn @ Wout + bout  (fp16 mma.sync)
    hgemm<true><<<dim3(DIM / BN, ROWS / BM), 256, G_SMEM>>>(
        ah, woh, bout, out, ROWS, DIM, DIM);
}

// round 14
// speedup vs baseline: 1.5079x; 1.3124x over previous
#include <cuda_runtime.h>
#include <cuda_fp16.h>
#include <cstdint>
#include <cstddef>

#define DIM      1024
#define HEADS    16
#define HEAD_DIM 64
#define BLK      32
#define FEAT     128
#define BATCH    4
#define SEQ      4096
#define NBLK     (SEQ / BLK)      // 128
#define ROWS     (BATCH * SEQ)    // 16384

// Scratch (allocation-free rule: __device__ globals)
__device__ float  g_qkv[(size_t)ROWS * 3 * DIM];             // 192 MB fp32
__device__ __half g_xh[(size_t)ROWS * DIM];                  // 32 MB
__device__ __half g_ah[(size_t)ROWS * DIM];                  // 32 MB
__device__ __half g_wqh[(size_t)3 * DIM * DIM];              // 6 MB
__device__ __half g_woh[(size_t)DIM * DIM];                  // 2 MB
__device__ __half g_pt[(size_t)HEADS * FEAT * HEAD_DIM];     // 256 KB projT [h][f][d]
__device__ __half g_qf[(size_t)BATCH * HEADS * SEQ * FEAT];  // 64 MB [b,h][n][f]
__device__ __half g_kf[(size_t)BATCH * HEADS * SEQ * FEAT];  // 64 MB

// ---------------------------------------------------------------------------
// helpers
// ---------------------------------------------------------------------------
__device__ __forceinline__ uint32_t smem_u32(const void* p) {
    uint32_t a;
    asm("{ .reg .u64 t; cvta.to.shared.u64 t, %1; cvt.u32.u64 %0, t; }" : "=r"(a) : "l"(p));
    return a;
}

#define SW128(off) ((off) ^ (((off) >> 3) & 0x70))

#define CP16(dst, src) \
    asm volatile("cp.async.cg.shared.global [%0], [%1], 16;" :: "r"(dst), "l"(src) : "memory")
#define CP_COMMIT() asm volatile("cp.async.commit_group;" ::: "memory")
#define CP_WAIT1()  asm volatile("cp.async.wait_group 1;" ::: "memory")
#define CP_WAIT0()  asm volatile("cp.async.wait_group 0;" ::: "memory")

#define LDSM4(r0, r1, r2, r3, addr)                                           \
    asm volatile("ldmatrix.sync.aligned.m8n8.x4.shared.b16 {%0,%1,%2,%3}, [%4];" \
                 : "=r"(r0), "=r"(r1), "=r"(r2), "=r"(r3) : "r"(addr))

#define LDSM4T(r0, r1, r2, r3, addr)                                          \
    asm volatile("ldmatrix.sync.aligned.m8n8.x4.trans.shared.b16 {%0,%1,%2,%3}, [%4];" \
                 : "=r"(r0), "=r"(r1), "=r"(r2), "=r"(r3) : "r"(addr))

#define MMA_F16(d, a0, a1, a2, a3, b0, b1)                                    \
    asm volatile("mma.sync.aligned.m16n8k16.row.col.f32.f16.f16.f32 "         \
                 "{%0,%1,%2,%3}, {%4,%5,%6,%7}, {%8,%9}, {%0,%1,%2,%3};"      \
                 : "+f"((d)[0]), "+f"((d)[1]), "+f"((d)[2]), "+f"((d)[3])     \
                 : "r"(a0), "r"(a1), "r"(a2), "r"(a3), "r"(b0), "r"(b1))

__device__ __forceinline__ float elu1(float x) {
    return (x > 0.0f) ? (x + 1.0f) : __expf(x);
}

// ---------------------------------------------------------------------------
// fp16 mma.sync GEMM (at HMMA dispatch wall, 2 CTAs/SM).
// ---------------------------------------------------------------------------
#define BM 128
#define BN 128
#define BKH 64
#define NSTAGE 3
#define TILE_B (BM * 128)
#define ST_BYTES (2 * TILE_B)
#define G_SMEM (NSTAGE * ST_BYTES) // 98304 B

template<bool BIAS>
__global__ __launch_bounds__(256, 2)
void hgemm(const __half* __restrict__ Ah, const __half* __restrict__ Bh,
           const float* __restrict__ bias, float* __restrict__ C,
           int M, int N, int K)
{
    extern __shared__ char smem[];
    const uint32_t sbase = smem_u32(smem);
    const int t = threadIdx.x;
    const int lid = t & 31, wid = t >> 5;
    const int wm = wid & 3, wn = wid >> 2;
    const int m0 = wm * 32, n0 = wn * 64;
    const int bn = blockIdx.x, bm = blockIdx.y;
    const int NK = K / BKH;

    const __half* Ahb = Ah + (size_t)bm * BM * K;
    const __half* Bhb = Bh + (size_t)bn * BN * K;

    const int prow = t >> 3;
    const int pch  = t & 7;

    auto load_stage = [&](int s, int kc) {
        const uint32_t sb0 = sbase + s * ST_BYTES;
        const int koff = kc * BKH;
#pragma unroll
        for (int i = 0; i < 4; i++) {
            int row = prow + i * 32;
            uint32_t off = SW128((uint32_t)(row * 128 + pch * 16));
            size_t g = (size_t)row * K + koff + pch * 8;
            CP16(sb0 + off,          Ahb + g);
            CP16(sb0 + TILE_B + off, Bhb + g);
        }
        CP_COMMIT();
    };

    const int lr = lid & 15;
    const int lk16 = (lid >> 4) * 16;
    const uint32_t aoff = (uint32_t)((m0 + lr) * 128 + lk16);
    uint32_t boff[4];
#pragma unroll
    for (int j = 0; j < 4; j++)
        boff[j] = (uint32_t)((n0 + 16 * j + lr) * 128 + lk16);

    float acc[2][8][4];
#pragma unroll
    for (int mi = 0; mi < 2; mi++)
#pragma unroll
        for (int f = 0; f < 8; f++)
#pragma unroll
            for (int r = 0; r < 4; r++) acc[mi][f][r] = 0.0f;

    load_stage(0, 0);
    load_stage(1, 1);

    for (int it = 0; it < NK; it++) {
        CP_WAIT1();
        __syncthreads();
        const int nxt = it + 2;
        if (nxt < NK) load_stage(nxt % NSTAGE, nxt);

        const uint32_t s0 = sbase + (it % NSTAGE) * ST_BYTES;
        const uint32_t sAh = s0;
        const uint32_t sBh = s0 + TILE_B;

#pragma unroll
        for (int ks = 0; ks < 4; ks++) {
            const uint32_t kb = ks * 32;
            uint32_t ah0[4], ah1[4];
            {
                uint32_t o0 = SW128(aoff + kb);
                uint32_t o1 = SW128(aoff + 16 * 128 + kb);
                LDSM4(ah0[0], ah0[1], ah0[2], ah0[3], sAh + o0);
                LDSM4(ah1[0], ah1[1], ah1[2], ah1[3], sAh + o1);
            }
#pragma unroll
            for (int j = 0; j < 4; j++) {
                uint32_t bh[4];
                uint32_t ob = SW128(boff[j] + kb);
                LDSM4(bh[0], bh[1], bh[2], bh[3], sBh + ob);

                MMA_F16(acc[0][2 * j + 0], ah0[0], ah0[1], ah0[2], ah0[3], bh[0], bh[2]);
                MMA_F16(acc[0][2 * j + 1], ah0[0], ah0[1], ah0[2], ah0[3], bh[1], bh[3]);
                MMA_F16(acc[1][2 * j + 0], ah1[0], ah1[1], ah1[2], ah1[3], bh[0], bh[2]);
                MMA_F16(acc[1][2 * j + 1], ah1[0], ah1[1], ah1[2], ah1[3], bh[1], bh[3]);
            }
        }
    }

    const int g = lid >> 2, tq = lid & 3;
#pragma unroll
    for (int mi = 0; mi < 2; mi++) {
        int rowl = m0 + mi * 16 + g;
#pragma unroll
        for (int f = 0; f < 8; f++) {
            int col = n0 + f * 8 + tq * 2;
            float b0 = 0.0f, b1 = 0.0f;
            if (BIAS) { b0 = bias[bn * BN + col]; b1 = bias[bn * BN + col + 1]; }
            float* p0 = C + (size_t)(bm * BM + rowl) * N + bn * BN + col;
            float* p1 = C + (size_t)(bm * BM + rowl + 8) * N + bn * BN + col;
            float2 v0 = { acc[mi][f][0] + b0, acc[mi][f][1] + b1 };
            float2 v1 = { acc[mi][f][2] + b0, acc[mi][f][3] + b1 };
            *(float2*)p0 = v0;
            *(float2*)p1 = v1;
        }
    }
}

// ---------------------------------------------------------------------------
// feat_gemm: qf/kf = elu([128 tokens, 64] @ projT_h^T) + 1 via HMMA.
// ---------------------------------------------------------------------------
#define FT_SMEM (3 * 16384)

__global__ __launch_bounds__(256)
void feat_gemm(const float* __restrict__ qkv, const __half* __restrict__ pt,
               __half* __restrict__ qf, __half* __restrict__ kf)
{
    extern __shared__ char smem[];
    const uint32_t sbase = smem_u32(smem);
    const uint32_t sQ = sbase, sK = sbase + 16384, sB = sbase + 32768;
    const int t = threadIdx.x;
    const int lid = t & 31, wid = t >> 5;
    const int wm = wid & 3, wn = wid >> 2;
    const int m0 = wm * 32, n0 = wn * 64;
    const int bh = blockIdx.x;
    const int nt = blockIdx.y;
    const int b = bh / HEADS, h = bh - b * HEADS;
    const size_t rowbase = (size_t)b * SEQ + nt * 128;

    {
        const __half* src = pt + (size_t)h * FEAT * HEAD_DIM;
        int r = t >> 1, half = (t & 1) * 64;
#pragma unroll
        for (int c = 0; c < 4; c++) {
            uint32_t off = SW128((uint32_t)(r * 128 + half + c * 16));
            CP16(sB + off, src + r * 64 + (half + c * 16) / 2);
        }
        CP_COMMIT();
    }
    {
        int r = t >> 1, half = t & 1;
        const float* qrow = qkv + (rowbase + r) * (3 * DIM) + h * HEAD_DIM + half * 32;
        const float* krow = qrow + DIM;
#pragma unroll
        for (int c = 0; c < 4; c++) {
            float4 a = *(const float4*)(qrow + c * 8);
            float4 d = *(const float4*)(qrow + c * 8 + 4);
            __half2 h0 = __floats2half2_rn(a.x, a.y), h1 = __floats2half2_rn(a.z, a.w);
            __half2 h2 = __floats2half2_rn(d.x, d.y), h3 = __floats2half2_rn(d.z, d.w);
            uint4 v = { *(uint32_t*)&h0, *(uint32_t*)&h1, *(uint32_t*)&h2, *(uint32_t*)&h3 };
            uint32_t off = SW128((uint32_t)(r * 128 + half * 64 + c * 16));
            *(uint4*)(smem + 0 + off) = v;

            a = *(const float4*)(krow + c * 8);
            d = *(const float4*)(krow + c * 8 + 4);
            h0 = __floats2half2_rn(a.x, a.y); h1 = __floats2half2_rn(a.z, a.w);
            h2 = __floats2half2_rn(d.x, d.y); h3 = __floats2half2_rn(d.z, d.w);
            uint4 w = { *(uint32_t*)&h0, *(uint32_t*)&h1, *(uint32_t*)&h2, *(uint32_t*)&h3 };
            *(uint4*)(smem + 16384 + off) = w;
        }
    }
    CP_WAIT0();
    __syncthreads();

    const int lr = lid & 15;
    const int lk16 = (lid >> 4) * 16;
    const uint32_t aoff = (uint32_t)((m0 + lr) * 128 + lk16);
    uint32_t boff[4];
#pragma unroll
    for (int j = 0; j < 4; j++)
        boff[j] = (uint32_t)((n0 + 16 * j + lr) * 128 + lk16);

    const int g = lid >> 2, tq = lid & 3;

#pragma unroll
    for (int op = 0; op < 2; op++) {
        const uint32_t sA = op ? sK : sQ;
        float acc[2][8][4];
#pragma unroll
        for (int mi = 0; mi < 2; mi++)
#pragma unroll
            for (int f = 0; f < 8; f++)
#pragma unroll
                for (int r = 0; r < 4; r++) acc[mi][f][r] = 0.0f;

#pragma unroll
        for (int ks = 0; ks < 4; ks++) {
            const uint32_t kb = ks * 32;
            uint32_t a0[4], a1[4];
            LDSM4(a0[0], a0[1], a0[2], a0[3], sA + SW128(aoff + kb));
            LDSM4(a1[0], a1[1], a1[2], a1[3], sA + SW128(aoff + 16 * 128 + kb));
#pragma unroll
            for (int j = 0; j < 4; j++) {
                uint32_t bfr[4];
                LDSM4(bfr[0], bfr[1], bfr[2], bfr[3], sB + SW128(boff[j] + kb));
                MMA_F16(acc[0][2 * j + 0], a0[0], a0[1], a0[2], a0[3], bfr[0], bfr[2]);
                MMA_F16(acc[0][2 * j + 1], a0[0], a0[1], a0[2], a0[3], bfr[1], bfr[3]);
                MMA_F16(acc[1][2 * j + 0], a1[0], a1[1], a1[2], a1[3], bfr[0], bfr[2]);
                MMA_F16(acc[1][2 * j + 1], a1[0], a1[1], a1[2], a1[3], bfr[1], bfr[3]);
            }
        }

        __half* dst = (op ? kf : qf) + ((size_t)bh * SEQ + nt * 128) * FEAT;
#pragma unroll
        for (int mi = 0; mi < 2; mi++) {
            int rowl = m0 + mi * 16 + g;
#pragma unroll
            for (int f = 0; f < 8; f++) {
                int col = n0 + f * 8 + tq * 2;
                __half2 v0 = __floats2half2_rn(elu1(acc[mi][f][0]), elu1(acc[mi][f][1]));
                __half2 v1 = __floats2half2_rn(elu1(acc[mi][f][2]), elu1(acc[mi][f][3]));
                *(__half2*)(dst + (size_t)rowl * FEAT + col)       = v0;
                *(__half2*)(dst + (size_t)(rowl + 8) * FEAT + col) = v1;
            }
        }
    }
}

// ---------------------------------------------------------------------------
// middle3: per (b,h,m) block, HMMA for kv = kf^T@v and out = qf@kv.
// trans ldmatrix for kf^T / v^T / kv^T; ksum+z exact fp32 scalar.
// Row pads: kf/qf 272B, v/kv 144B -> all LDSM phases conflict-free.
// ---------------------------------------------------------------------------
#define KFB 272
#define VB  144
#define KVB 144
#define M3_KF   0                      // 32 x 272 = 8704
#define M3_QF   8704                   // 8704
#define M3_V    17408                  // 32 x 144 = 4608
#define M3_KV   22016                  // 128 x 144 = 18432
#define M3_KSUM 40448                  // 128 f32
#define M3_Z    40960                  // 32 f32
#define M3_SMEM 41088

__global__ __launch_bounds__(256)
void middle3(const float* __restrict__ qkv,
             const __half* __restrict__ qf, const __half* __restrict__ kf,
             __half* __restrict__ attn_h)
{
    extern __shared__ char sm[];
    const uint32_t sb = smem_u32(sm);
    const int t = threadIdx.x;
    const int lid = t & 31, wid = t >> 5;
    const int gb = blockIdx.x;
    const int b = gb / (HEADS * NBLK);
    const int rem = gb - b * (HEADS * NBLK);
    const int h = rem / NBLK;
    const int m = rem - h * NBLK;

    // ---- load kf/qf (fp16, 256B rows -> 272B padded rows) ----
    {
        const __half* ks = kf + ((size_t)(b * HEADS + h) * SEQ + m * BLK) * FEAT;
        const __half* qs = qf + ((size_t)(b * HEADS + h) * SEQ + m * BLK) * FEAT;
        for (int i = t; i < 512; i += 256) {
            int r = i >> 4, c = i & 15;
            *(uint4*)(sm + M3_KF + r * KFB + c * 16) = *(const uint4*)(ks + r * FEAT + c * 8);
            *(uint4*)(sm + M3_QF + r * KFB + c * 16) = *(const uint4*)(qs + r * FEAT + c * 8);
        }
    }
    // ---- v: fp32 -> fp16, 144B padded rows ----
    {
        int r = t >> 3, d0 = (t & 7) * 8;
        const float* vr = qkv + ((size_t)(b * SEQ + m * BLK + r)) * (3 * DIM)
                        + 2 * DIM + h * HEAD_DIM + d0;
        float4 a = *(const float4*)vr;
        float4 c = *(const float4*)(vr + 4);
        __half2 h0 = __floats2half2_rn(a.x, a.y), h1 = __floats2half2_rn(a.z, a.w);
        __half2 h2 = __floats2half2_rn(c.x, c.y), h3 = __floats2half2_rn(c.z, c.w);
        uint4 pk = { *(uint32_t*)&h0, *(uint32_t*)&h1, *(uint32_t*)&h2, *(uint32_t*)&h3 };
        *(uint4*)(sm + M3_V + r * VB + d0 * 2) = pk;
    }
    __syncthreads();

    // ---- ksum[f] = sum_s kf[s][f] (fp32, t<128) ----
    if (t < FEAT) {
        float acc = 0.0f;
        for (int s = 0; s < BLK; s++)
            acc += __half2float(*(const __half*)(sm + M3_KF + s * KFB + t * 2));
        *(float*)(sm + M3_KSUM + t * 4) = acc;
    }

    // ---- MMA1: kv[f][d] = kf^T @ v  (M=128 f, N=64 d, K=32 s) ----
    // warp w owns f-range [16w, 16w+16)
    const int f0 = wid * 16;
    const int trow = (lid & 7) + ((lid >> 4) & 1) * 8;   // s (or f for MMA2 B)
    const int tcol8 = ((lid >> 3) & 1) * 8;              // +8 column half
    float acc1[8][4];
#pragma unroll
    for (int j = 0; j < 8; j++)
#pragma unroll
        for (int r = 0; r < 4; r++) acc1[j][r] = 0.0f;

#pragma unroll
    for (int ksi = 0; ksi < 2; ksi++) {
        uint32_t a[4];
        LDSM4T(a[0], a[1], a[2], a[3],
               sb + M3_KF + (uint32_t)((trow + ksi * 16) * KFB + (f0 + tcol8) * 2));
#pragma unroll
        for (int nj = 0; nj < 4; nj++) {
            uint32_t bf[4];
            LDSM4T(bf[0], bf[1], bf[2], bf[3],
                   sb + M3_V + (uint32_t)((trow + ksi * 16) * VB + (nj * 16 + tcol8) * 2));
            MMA_F16(acc1[2 * nj + 0], a[0], a[1], a[2], a[3], bf[0], bf[2]);
            MMA_F16(acc1[2 * nj + 1], a[0], a[1], a[2], a[3], bf[1], bf[3]);
        }
    }
    __syncthreads();   // ksum visible; v/kf reads done

    // ---- store kv fp16; z (t<32) in parallel ----
    {
        const int g = lid >> 2, tq = lid & 3;
#pragma unroll
        for (int j = 0; j < 8; j++) {
            int d0 = j * 8 + tq * 2;
            __half2 lo = __floats2half2_rn(acc1[j][0], acc1[j][1]);
            __half2 hi = __floats2half2_rn(acc1[j][2], acc1[j][3]);
            *(__half2*)(sm + M3_KV + (f0 + g) * KVB + d0 * 2)     = lo;
            *(__half2*)(sm + M3_KV + (f0 + g + 8) * KVB + d0 * 2) = hi;
        }
    }
    if (t < BLK) {
        float acc = 0.0f;
        for (int f = 0; f < FEAT; f++)
            acc += __half2float(*(const __half*)(sm + M3_QF + t * KFB + f * 2))
                 * *(const float*)(sm + M3_KSUM + f * 4);
        *(float*)(sm + M3_Z + t * 4) = 1.0f / (acc + 1e-8f);
    }
    __syncthreads();

    // ---- MMA2: out[s][d] = qf @ kv  (M=32 s, N=64 d, K=128 f) ----
    const int wm2 = wid & 1, wn2 = wid >> 1;       // 2(M) x 4(N) warps
    const int s0 = wm2 * 16, d0 = wn2 * 16;
    float acc2[2][4];
#pragma unroll
    for (int j = 0; j < 2; j++)
#pragma unroll
        for (int r = 0; r < 4; r++) acc2[j][r] = 0.0f;

    const uint32_t qoff = (uint32_t)(M3_QF + (s0 + (lid & 15)) * KFB + (lid >> 4) * 16);
#pragma unroll
    for (int ksi = 0; ksi < 8; ksi++) {
        uint32_t a[4];
        LDSM4(a[0], a[1], a[2], a[3], sb + qoff + ksi * 32);
        uint32_t bf[4];
        LDSM4T(bf[0], bf[1], bf[2], bf[3],
               sb + M3_KV + (uint32_t)((ksi * 16 + trow) * KVB + (d0 + tcol8) * 2));
        MMA_F16(acc2[0], a[0], a[1], a[2], a[3], bf[0], bf[2]);
        MMA_F16(acc2[1], a[0], a[1], a[2], a[3], bf[1], bf[3]);
    }

    // ---- epilogue: scale by z, write fp16 attn ----
    {
        const int g = lid >> 2, tq = lid & 3;
        const int rowbase = b * SEQ + m * BLK;
#pragma unroll
        for (int half = 0; half < 2; half++) {
            int s = s0 + g + half * 8;
            float z = *(const float*)(sm + M3_Z + s * 4);
            size_t off = (size_t)(rowbase + s) * DIM + h * HEAD_DIM;
            __half2 v0 = __floats2half2_rn(acc2[0][2 * half] * z, acc2[0][2 * half + 1] * z);
            __half2 v1 = __floats2half2_rn(acc2[1][2 * half] * z, acc2[1][2 * half + 1] * z);
            *(__half2*)(attn_h + off + d0 + tq * 2)     = v0;
            *(__half2*)(attn_h + off + d0 + 8 + tq * 2) = v1;
        }
    }
}

// ---------------------------------------------------------------------------
// prep kernels
// ---------------------------------------------------------------------------
__global__ void round_kernel(const float* __restrict__ in, __half* __restrict__ h,
                             int n4)
{
    int i = blockIdx.x * blockDim.x + threadIdx.x;
    if (i >= n4) return;
    float4 v = ((const float4*)in)[i];
    ((__half2*)h)[2 * i]     = __halves2half2(__float2half_rn(v.x), __float2half_rn(v.y));
    ((__half2*)h)[2 * i + 1] = __halves2half2(__float2half_rn(v.z), __float2half_rn(v.w));
}

__global__ void transpose_h(const float* __restrict__ in,
                            __half* __restrict__ oh, int R, int C)
{
    __shared__ float tile[32][33];
    int bx = blockIdx.x * 32, by = blockIdx.y * 32;
#pragma unroll
    for (int i = 0; i < 32; i += 8)
        tile[threadIdx.y + i][threadIdx.x] =
            in[(size_t)(by + threadIdx.y + i) * C + bx + threadIdx.x];
    __syncthreads();
#pragma unroll
    for (int i = 0; i < 32; i += 8) {
        size_t idx = (size_t)(bx + threadIdx.y + i) * R + by + threadIdx.x;
        oh[idx] = __float2half_rn(tile[threadIdx.x][threadIdx.y + i]);
    }
}

__global__ void transpose_ph(const float* __restrict__ in, __half* __restrict__ out)
{
    __shared__ float tile[32][33];
    int hh = blockIdx.z;
    int bx = blockIdx.x * 32;
    int by = blockIdx.y * 32;
    const float* src = in + (size_t)hh * HEAD_DIM * FEAT;
    __half* dst = out + (size_t)hh * FEAT * HEAD_DIM;
#pragma unroll
    for (int i = 0; i < 32; i += 8)
        tile[threadIdx.y + i][threadIdx.x] =
            src[(size_t)(by + threadIdx.y + i) * FEAT + bx + threadIdx.x];
    __syncthreads();
#pragma unroll
    for (int i = 0; i < 32; i += 8)
        dst[(size_t)(bx + threadIdx.y + i) * HEAD_DIM + by + threadIdx.x] =
            __float2half_rn(tile[threadIdx.x][threadIdx.y + i]);
}

// ---------------------------------------------------------------------------
extern "C" void kernel_launch(void* const* d_in, const int* in_sizes, int n_in,
                              void* d_out, int out_size)
{
    const float* x    = (const float*)d_in[0];
    const float* Wqkv = (const float*)d_in[1];
    const float* proj = (const float*)d_in[2];
    const float* Wout = (const float*)d_in[3];
    const float* bout = (const float*)d_in[4];
    float* out = (float*)d_out;

    float*  qkv; cudaGetSymbolAddress((void**)&qkv, g_qkv);
    __half *xh, *ah, *wqh, *woh, *pt, *qfp, *kfp;
    cudaGetSymbolAddress((void**)&xh,  g_xh);
    cudaGetSymbolAddress((void**)&ah,  g_ah);
    cudaGetSymbolAddress((void**)&wqh, g_wqh);
    cudaGetSymbolAddress((void**)&woh, g_woh);
    cudaGetSymbolAddress((void**)&pt,  g_pt);
    cudaGetSymbolAddress((void**)&qfp, g_qf);
    cudaGetSymbolAddress((void**)&kfp, g_kf);

    cudaFuncSetAttribute(hgemm<false>, cudaFuncAttributeMaxDynamicSharedMemorySize, G_SMEM);
    cudaFuncSetAttribute(hgemm<true>,  cudaFuncAttributeMaxDynamicSharedMemorySize, G_SMEM);
    cudaFuncSetAttribute(feat_gemm,    cudaFuncAttributeMaxDynamicSharedMemorySize, FT_SMEM);
    cudaFuncSetAttribute(middle3,      cudaFuncAttributeMaxDynamicSharedMemorySize, M3_SMEM);

    // 0) operand prep
    {
        int n4 = ROWS * DIM / 4;
        round_kernel<<<(n4 + 255) / 256, 256>>>(x, xh, n4);
    }
    transpose_h<<<dim3((3 * DIM) / 32, DIM / 32), dim3(32, 8)>>>(Wqkv, wqh, DIM, 3 * DIM);
    transpose_h<<<dim3(DIM / 32, DIM / 32), dim3(32, 8)>>>(Wout, woh, DIM, DIM);
    transpose_ph<<<dim3(FEAT / 32, HEAD_DIM / 32, HEADS), dim3(32, 8)>>>(proj, pt);

    // 1) qkv = x @ Wqkv
    hgemm<false><<<dim3((3 * DIM) / BN, ROWS / BM), 256, G_SMEM>>>(
        xh, wqh, nullptr, qkv, ROWS, 3 * DIM, DIM);

    // 2a) qf/kf = elu(q/k @ proj_h)+1 (HMMA)
    feat_gemm<<<dim3(BATCH * HEADS, SEQ / 128), 256, FT_SMEM>>>(qkv, pt, qfp, kfp);

    // 2b) per-block kv/z/out (HMMA)
    middle3<<<BATCH * HEADS * NBLK, 256, M3_SMEM>>>(qkv, qfp, kfp, ah);

    // 3) out = attn @ Wout + bout
    hgemm<true><<<dim3(DIM / BN, ROWS / BM), 256, G_SMEM>>>(
        ah, woh, bout, out, ROWS, DIM, DIM);
}

// round 15
// speedup vs baseline: 1.6872x; 1.1190x over previous
#include <cuda_runtime.h>
#include <cuda_fp16.h>
#include <cstdint>
#include <cstddef>

#define DIM      1024
#define HEADS    16
#define HEAD_DIM 64
#define BLK      32
#define FEAT     128
#define BATCH    4
#define SEQ      4096
#define NBLK     (SEQ / BLK)      // 128
#define ROWS     (BATCH * SEQ)    // 16384

// Scratch (allocation-free rule: __device__ globals)
__device__ __half g_qkvh[(size_t)ROWS * 3 * DIM];            // 96 MB fp16
__device__ __half g_xh[(size_t)ROWS * DIM];                  // 32 MB
__device__ __half g_ah[(size_t)ROWS * DIM];                  // 32 MB
__device__ __half g_wqh[(size_t)3 * DIM * DIM];              // 6 MB
__device__ __half g_woh[(size_t)DIM * DIM];                  // 2 MB
__device__ __half g_pt[(size_t)HEADS * FEAT * HEAD_DIM];     // 256 KB projT [h][f][d]

// ---------------------------------------------------------------------------
// helpers
// ---------------------------------------------------------------------------
__device__ __forceinline__ uint32_t smem_u32(const void* p) {
    uint32_t a;
    asm("{ .reg .u64 t; cvta.to.shared.u64 t, %1; cvt.u32.u64 %0, t; }" : "=r"(a) : "l"(p));
    return a;
}

#define SW128(off) ((off) ^ (((off) >> 3) & 0x70))

#define CP16(dst, src) \
    asm volatile("cp.async.cg.shared.global [%0], [%1], 16;" :: "r"(dst), "l"(src) : "memory")
#define CP_COMMIT() asm volatile("cp.async.commit_group;" ::: "memory")
#define CP_WAIT1()  asm volatile("cp.async.wait_group 1;" ::: "memory")
#define CP_WAIT0()  asm volatile("cp.async.wait_group 0;" ::: "memory")

#define LDSM4(r0, r1, r2, r3, addr)                                           \
    asm volatile("ldmatrix.sync.aligned.m8n8.x4.shared.b16 {%0,%1,%2,%3}, [%4];" \
                 : "=r"(r0), "=r"(r1), "=r"(r2), "=r"(r3) : "r"(addr))

#define LDSM4T(r0, r1, r2, r3, addr)                                          \
    asm volatile("ldmatrix.sync.aligned.m8n8.x4.trans.shared.b16 {%0,%1,%2,%3}, [%4];" \
                 : "=r"(r0), "=r"(r1), "=r"(r2), "=r"(r3) : "r"(addr))

#define MMA_F16(d, a0, a1, a2, a3, b0, b1)                                    \
    asm volatile("mma.sync.aligned.m16n8k16.row.col.f32.f16.f16.f32 "         \
                 "{%0,%1,%2,%3}, {%4,%5,%6,%7}, {%8,%9}, {%0,%1,%2,%3};"      \
                 : "+f"((d)[0]), "+f"((d)[1]), "+f"((d)[2]), "+f"((d)[3])     \
                 : "r"(a0), "r"(a1), "r"(a2), "r"(a3), "r"(b0), "r"(b1))

__device__ __forceinline__ float elu1(float x) {
    return (x > 0.0f) ? (x + 1.0f) : __expf(x);
}

// ---------------------------------------------------------------------------
// fp16 mma.sync GEMM (at HMMA dispatch wall, 2 CTAs/SM). OUT16 selects fp16 C.
// ---------------------------------------------------------------------------
#define BM 128
#define BN 128
#define BKH 64
#define NSTAGE 3
#define TILE_B (BM * 128)
#define ST_BYTES (2 * TILE_B)
#define G_SMEM (NSTAGE * ST_BYTES) // 98304 B

template<bool BIAS, bool OUT16>
__global__ __launch_bounds__(256, 2)
void hgemm(const __half* __restrict__ Ah, const __half* __restrict__ Bh,
           const float* __restrict__ bias, float* __restrict__ Cf,
           __half* __restrict__ Ch, int M, int N, int K)
{
    extern __shared__ char smem[];
    const uint32_t sbase = smem_u32(smem);
    const int t = threadIdx.x;
    const int lid = t & 31, wid = t >> 5;
    const int wm = wid & 3, wn = wid >> 2;
    const int m0 = wm * 32, n0 = wn * 64;
    const int bn = blockIdx.x, bm = blockIdx.y;
    const int NK = K / BKH;

    const __half* Ahb = Ah + (size_t)bm * BM * K;
    const __half* Bhb = Bh + (size_t)bn * BN * K;

    const int prow = t >> 3;
    const int pch  = t & 7;

    auto load_stage = [&](int s, int kc) {
        const uint32_t sb0 = sbase + s * ST_BYTES;
        const int koff = kc * BKH;
#pragma unroll
        for (int i = 0; i < 4; i++) {
            int row = prow + i * 32;
            uint32_t off = SW128((uint32_t)(row * 128 + pch * 16));
            size_t g = (size_t)row * K + koff + pch * 8;
            CP16(sb0 + off,          Ahb + g);
            CP16(sb0 + TILE_B + off, Bhb + g);
        }
        CP_COMMIT();
    };

    const int lr = lid & 15;
    const int lk16 = (lid >> 4) * 16;
    const uint32_t aoff = (uint32_t)((m0 + lr) * 128 + lk16);
    uint32_t boff[4];
#pragma unroll
    for (int j = 0; j < 4; j++)
        boff[j] = (uint32_t)((n0 + 16 * j + lr) * 128 + lk16);

    float acc[2][8][4];
#pragma unroll
    for (int mi = 0; mi < 2; mi++)
#pragma unroll
        for (int f = 0; f < 8; f++)
#pragma unroll
            for (int r = 0; r < 4; r++) acc[mi][f][r] = 0.0f;

    load_stage(0, 0);
    load_stage(1, 1);

    for (int it = 0; it < NK; it++) {
        CP_WAIT1();
        __syncthreads();
        const int nxt = it + 2;
        if (nxt < NK) load_stage(nxt % NSTAGE, nxt);

        const uint32_t s0 = sbase + (it % NSTAGE) * ST_BYTES;
        const uint32_t sAh = s0;
        const uint32_t sBh = s0 + TILE_B;

#pragma unroll
        for (int ks = 0; ks < 4; ks++) {
            const uint32_t kb = ks * 32;
            uint32_t ah0[4], ah1[4];
            {
                uint32_t o0 = SW128(aoff + kb);
                uint32_t o1 = SW128(aoff + 16 * 128 + kb);
                LDSM4(ah0[0], ah0[1], ah0[2], ah0[3], sAh + o0);
                LDSM4(ah1[0], ah1[1], ah1[2], ah1[3], sAh + o1);
            }
#pragma unroll
            for (int j = 0; j < 4; j++) {
                uint32_t bh[4];
                uint32_t ob = SW128(boff[j] + kb);
                LDSM4(bh[0], bh[1], bh[2], bh[3], sBh + ob);

                MMA_F16(acc[0][2 * j + 0], ah0[0], ah0[1], ah0[2], ah0[3], bh[0], bh[2]);
                MMA_F16(acc[0][2 * j + 1], ah0[0], ah0[1], ah0[2], ah0[3], bh[1], bh[3]);
                MMA_F16(acc[1][2 * j + 0], ah1[0], ah1[1], ah1[2], ah1[3], bh[0], bh[2]);
                MMA_F16(acc[1][2 * j + 1], ah1[0], ah1[1], ah1[2], ah1[3], bh[1], bh[3]);
            }
        }
    }

    const int g = lid >> 2, tq = lid & 3;
#pragma unroll
    for (int mi = 0; mi < 2; mi++) {
        int rowl = m0 + mi * 16 + g;
#pragma unroll
        for (int f = 0; f < 8; f++) {
            int col = n0 + f * 8 + tq * 2;
            if (OUT16) {
                __half* p0 = Ch + (size_t)(bm * BM + rowl) * N + bn * BN + col;
                __half* p1 = Ch + (size_t)(bm * BM + rowl + 8) * N + bn * BN + col;
                *(__half2*)p0 = __floats2half2_rn(acc[mi][f][0], acc[mi][f][1]);
                *(__half2*)p1 = __floats2half2_rn(acc[mi][f][2], acc[mi][f][3]);
            } else {
                float b0 = 0.0f, b1 = 0.0f;
                if (BIAS) { b0 = bias[bn * BN + col]; b1 = bias[bn * BN + col + 1]; }
                float* p0 = Cf + (size_t)(bm * BM + rowl) * N + bn * BN + col;
                float* p1 = Cf + (size_t)(bm * BM + rowl + 8) * N + bn * BN + col;
                float2 v0 = { acc[mi][f][0] + b0, acc[mi][f][1] + b1 };
                float2 v1 = { acc[mi][f][2] + b0, acc[mi][f][3] + b1 };
                *(float2*)p0 = v0;
                *(float2*)p1 = v1;
            }
        }
    }
}

// ---------------------------------------------------------------------------
// fused_attn: per (b*h, 128-token tile):
//   stage q/k/proj (SW128) + v (padded rows) via cp.async (all fp16),
//   feat MMAs -> qf/kf in smem (272B padded rows),
//   then 4x 32-token blocks: kv = kf^T@v (HMMA), ksum/z fp32, out = qf@kv (HMMA).
// sKV aliases the dead q/k staging region. 137856 B smem, 1 CTA/SM.
// ---------------------------------------------------------------------------
#define KFB 272
#define VB  144
#define KVB 144
#define FS_Q    0
#define FS_K    16384
#define FS_KV   0                       // alias over FS_Q/FS_K (dead after feat)
#define FS_B    32768
#define FS_QF   49152                   // 128 x 272
#define FS_KF   (FS_QF + 128 * KFB)     // 83968
#define FS_V    (FS_KF + 128 * KFB)     // 118784, 128 x 144
#define FS_KSUM (FS_V + 128 * VB)       // 137216, 128 f32
#define FS_Z    (FS_KSUM + 512)         // 137728, 32 f32
#define FS_SMEM (FS_Z + 128)            // 137856

__global__ __launch_bounds__(256)
void fused_attn(const __half* __restrict__ qkvh, const __half* __restrict__ pt,
                __half* __restrict__ attn_h)
{
    extern __shared__ char sm[];
    const uint32_t sb = smem_u32(sm);
    const int t = threadIdx.x;
    const int lid = t & 31, wid = t >> 5;
    const int bh = blockIdx.x, nt = blockIdx.y;
    const int b = bh / HEADS, h = bh - b * HEADS;
    const size_t rowbase = (size_t)b * SEQ + nt * 128;

    // ---- stage q, k, v, projT via cp.async (16 x 16B per thread) ----
    {
        int r = t >> 1, half = t & 1;
        const __half* qrow = qkvh + (rowbase + r) * (3 * DIM) + h * HEAD_DIM + half * 32;
        const __half* krow = qrow + DIM;
        const __half* vrow = qrow + 2 * DIM;
        const __half* brow = pt + (size_t)h * FEAT * HEAD_DIM + r * 64 + half * 32;
#pragma unroll
        for (int c = 0; c < 4; c++) {
            uint32_t qk = SW128((uint32_t)(r * 128 + half * 64 + c * 16));
            CP16(sb + FS_Q + qk, qrow + c * 8);
            CP16(sb + FS_K + qk, krow + c * 8);
            CP16(sb + FS_B + qk, brow + c * 8);
            CP16(sb + FS_V + (uint32_t)(r * VB + half * 64 + c * 16), vrow + c * 8);
        }
        CP_COMMIT();
    }
    CP_WAIT0();
    __syncthreads();

    // ---- feat: qf/kf = elu([128,64] @ projT^T)+1 -> smem padded rows ----
    {
        const int wm = wid & 3, wn = wid >> 2;
        const int m0 = wm * 32, n0 = wn * 64;
        const int lr = lid & 15;
        const int lk16 = (lid >> 4) * 16;
        const uint32_t aoff = (uint32_t)((m0 + lr) * 128 + lk16);
        uint32_t boff[4];
#pragma unroll
        for (int j = 0; j < 4; j++)
            boff[j] = (uint32_t)((n0 + 16 * j + lr) * 128 + lk16);
        const int g = lid >> 2, tq = lid & 3;

#pragma unroll
        for (int op = 0; op < 2; op++) {
            const uint32_t sA = sb + (op ? FS_K : FS_Q);
            float acc[2][8][4];
#pragma unroll
            for (int mi = 0; mi < 2; mi++)
#pragma unroll
                for (int f = 0; f < 8; f++)
#pragma unroll
                    for (int r = 0; r < 4; r++) acc[mi][f][r] = 0.0f;

#pragma unroll
            for (int ks = 0; ks < 4; ks++) {
                const uint32_t kb = ks * 32;
                uint32_t a0[4], a1[4];
                LDSM4(a0[0], a0[1], a0[2], a0[3], sA + SW128(aoff + kb));
                LDSM4(a1[0], a1[1], a1[2], a1[3], sA + SW128(aoff + 16 * 128 + kb));
#pragma unroll
                for (int j = 0; j < 4; j++) {
                    uint32_t bfr[4];
                    LDSM4(bfr[0], bfr[1], bfr[2], bfr[3], sb + FS_B + SW128(boff[j] + kb));
                    MMA_F16(acc[0][2 * j + 0], a0[0], a0[1], a0[2], a0[3], bfr[0], bfr[2]);
                    MMA_F16(acc[0][2 * j + 1], a0[0], a0[1], a0[2], a0[3], bfr[1], bfr[3]);
                    MMA_F16(acc[1][2 * j + 0], a1[0], a1[1], a1[2], a1[3], bfr[0], bfr[2]);
                    MMA_F16(acc[1][2 * j + 1], a1[0], a1[1], a1[2], a1[3], bfr[1], bfr[3]);
                }
            }

            char* dst = sm + (op ? FS_KF : FS_QF);
#pragma unroll
            for (int mi = 0; mi < 2; mi++) {
                int rowl = m0 + mi * 16 + g;
#pragma unroll
                for (int f = 0; f < 8; f++) {
                    int col = n0 + f * 8 + tq * 2;
                    *(__half2*)(dst + rowl * KFB + col * 2) =
                        __floats2half2_rn(elu1(acc[mi][f][0]), elu1(acc[mi][f][1]));
                    *(__half2*)(dst + (rowl + 8) * KFB + col * 2) =
                        __floats2half2_rn(elu1(acc[mi][f][2]), elu1(acc[mi][f][3]));
                }
            }
        }
    }
    __syncthreads();   // qf/kf visible; q/k staging dead -> sKV alias safe

    // ---- per 32-token block: kv (HMMA), ksum/z (fp32), out (HMMA) ----
    const int f0 = wid * 16;
    const int trow = (lid & 7) + ((lid >> 4) & 1) * 8;
    const int tcol8 = ((lid >> 3) & 1) * 8;
    const int wm2 = wid & 1, wn2 = wid >> 1;
    const int s0 = wm2 * 16, d0 = wn2 * 16;
    const int g = lid >> 2, tq = lid & 3;

    for (int m2 = 0; m2 < 4; m2++) {
        const int sr = m2 * 32;

        // ksum (t<128) + MMA1 accumulate (regs only; no smem writes yet)
        float ks_acc = 0.0f;
        if (t < FEAT) {
            for (int s = 0; s < BLK; s++)
                ks_acc += __half2float(*(const __half*)(sm + FS_KF + (sr + s) * KFB + t * 2));
        }
        float acc1[8][4];
#pragma unroll
        for (int j = 0; j < 8; j++)
#pragma unroll
            for (int r = 0; r < 4; r++) acc1[j][r] = 0.0f;

#pragma unroll
        for (int ksi = 0; ksi < 2; ksi++) {
            uint32_t a[4];
            LDSM4T(a[0], a[1], a[2], a[3],
                   sb + FS_KF + (uint32_t)((sr + trow + ksi * 16) * KFB + (f0 + tcol8) * 2));
#pragma unroll
            for (int nj = 0; nj < 4; nj++) {
                uint32_t bf[4];
                LDSM4T(bf[0], bf[1], bf[2], bf[3],
                       sb + FS_V + (uint32_t)((sr + trow + ksi * 16) * VB + (nj * 16 + tcol8) * 2));
                MMA_F16(acc1[2 * nj + 0], a[0], a[1], a[2], a[3], bf[0], bf[2]);
                MMA_F16(acc1[2 * nj + 1], a[0], a[1], a[2], a[3], bf[1], bf[3]);
            }
        }

        // write kv + ksum
        if (t < FEAT) *(float*)(sm + FS_KSUM + t * 4) = ks_acc;
#pragma unroll
        for (int j = 0; j < 8; j++) {
            int dd = j * 8 + tq * 2;
            *(__half2*)(sm + FS_KV + (f0 + g) * KVB + dd * 2) =
                __floats2half2_rn(acc1[j][0], acc1[j][1]);
            *(__half2*)(sm + FS_KV + (f0 + g + 8) * KVB + dd * 2) =
                __floats2half2_rn(acc1[j][2], acc1[j][3]);
        }
        __syncthreads();

        // z (t<32) + MMA2
        if (t < BLK) {
            float za = 0.0f;
            for (int f = 0; f < FEAT; f++)
                za += __half2float(*(const __half*)(sm + FS_QF + (sr + t) * KFB + f * 2))
                    * *(const float*)(sm + FS_KSUM + f * 4);
            *(float*)(sm + FS_Z + t * 4) = 1.0f / (za + 1e-8f);
        }
        float acc2[2][4];
#pragma unroll
        for (int j = 0; j < 2; j++)
#pragma unroll
            for (int r = 0; r < 4; r++) acc2[j][r] = 0.0f;

        const uint32_t qoff = (uint32_t)(FS_QF + (sr + s0 + (lid & 15)) * KFB + (lid >> 4) * 16);
#pragma unroll
        for (int ksi = 0; ksi < 8; ksi++) {
            uint32_t a[4];
            LDSM4(a[0], a[1], a[2], a[3], sb + qoff + ksi * 32);
            uint32_t bf[4];
            LDSM4T(bf[0], bf[1], bf[2], bf[3],
                   sb + FS_KV + (uint32_t)((ksi * 16 + trow) * KVB + (d0 + tcol8) * 2));
            MMA_F16(acc2[0], a[0], a[1], a[2], a[3], bf[0], bf[2]);
            MMA_F16(acc2[1], a[0], a[1], a[2], a[3], bf[1], bf[3]);
        }
        __syncthreads();

        // epilogue: scale by z, write fp16 attn
#pragma unroll
        for (int half = 0; half < 2; half++) {
            int s = s0 + g + half * 8;
            float z = *(const float*)(sm + FS_Z + s * 4);
            size_t off = (rowbase + sr + s) * DIM + h * HEAD_DIM;
            *(__half2*)(attn_h + off + d0 + tq * 2) =
                __floats2half2_rn(acc2[0][2 * half] * z, acc2[0][2 * half + 1] * z);
            *(__half2*)(attn_h + off + d0 + 8 + tq * 2) =
                __floats2half2_rn(acc2[1][2 * half] * z, acc2[1][2 * half + 1] * z);
        }
    }
}

// ---------------------------------------------------------------------------
// prep kernels
// ---------------------------------------------------------------------------
__global__ void round_kernel(const float* __restrict__ in, __half* __restrict__ h,
                             int n4)
{
    int i = blockIdx.x * blockDim.x + threadIdx.x;
    if (i >= n4) return;
    float4 v = ((const float4*)in)[i];
    ((__half2*)h)[2 * i]     = __halves2half2(__float2half_rn(v.x), __float2half_rn(v.y));
    ((__half2*)h)[2 * i + 1] = __halves2half2(__float2half_rn(v.z), __float2half_rn(v.w));
}

__global__ void transpose_h(const float* __restrict__ in,
                            __half* __restrict__ oh, int R, int C)
{
    __shared__ float tile[32][33];
    int bx = blockIdx.x * 32, by = blockIdx.y * 32;
#pragma unroll
    for (int i = 0; i < 32; i += 8)
        tile[threadIdx.y + i][threadIdx.x] =
            in[(size_t)(by + threadIdx.y + i) * C + bx + threadIdx.x];
    __syncthreads();
#pragma unroll
    for (int i = 0; i < 32; i += 8) {
        size_t idx = (size_t)(bx + threadIdx.y + i) * R + by + threadIdx.x;
        oh[idx] = __float2half_rn(tile[threadIdx.x][threadIdx.y + i]);
    }
}

__global__ void transpose_ph(const float* __restrict__ in, __half* __restrict__ out)
{
    __shared__ float tile[32][33];
    int hh = blockIdx.z;
    int bx = blockIdx.x * 32;
    int by = blockIdx.y * 32;
    const float* src = in + (size_t)hh * HEAD_DIM * FEAT;
    __half* dst = out + (size_t)hh * FEAT * HEAD_DIM;
#pragma unroll
    for (int i = 0; i < 32; i += 8)
        tile[threadIdx.y + i][threadIdx.x] =
            src[(size_t)(by + threadIdx.y + i) * FEAT + bx + threadIdx.x];
    __syncthreads();
#pragma unroll
    for (int i = 0; i < 32; i += 8)
        dst[(size_t)(bx + threadIdx.y + i) * HEAD_DIM + by + threadIdx.x] =
            __float2half_rn(tile[threadIdx.x][threadIdx.y + i]);
}

// ---------------------------------------------------------------------------
extern "C" void kernel_launch(void* const* d_in, const int* in_sizes, int n_in,
                              void* d_out, int out_size)
{
    const float* x    = (const float*)d_in[0];
    const float* Wqkv = (const float*)d_in[1];
    const float* proj = (const float*)d_in[2];
    const float* Wout = (const float*)d_in[3];
    const float* bout = (const float*)d_in[4];
    float* out = (float*)d_out;

    __half *qkvh, *xh, *ah, *wqh, *woh, *pt;
    cudaGetSymbolAddress((void**)&qkvh, g_qkvh);
    cudaGetSymbolAddress((void**)&xh,   g_xh);
    cudaGetSymbolAddress((void**)&ah,   g_ah);
    cudaGetSymbolAddress((void**)&wqh,  g_wqh);
    cudaGetSymbolAddress((void**)&woh,  g_woh);
    cudaGetSymbolAddress((void**)&pt,   g_pt);

    cudaFuncSetAttribute((const void*)hgemm<false, true>,
                         cudaFuncAttributeMaxDynamicSharedMemorySize, G_SMEM);
    cudaFuncSetAttribute((const void*)hgemm<true, false>,
                         cudaFuncAttributeMaxDynamicSharedMemorySize, G_SMEM);
    cudaFuncSetAttribute((const void*)fused_attn,
                         cudaFuncAttributeMaxDynamicSharedMemorySize, FS_SMEM);

    // 0) operand prep
    {
        int n4 = ROWS * DIM / 4;
        round_kernel<<<(n4 + 255) / 256, 256>>>(x, xh, n4);
    }
    transpose_h<<<dim3((3 * DIM) / 32, DIM / 32), dim3(32, 8)>>>(Wqkv, wqh, DIM, 3 * DIM);
    transpose_h<<<dim3(DIM / 32, DIM / 32), dim3(32, 8)>>>(Wout, woh, DIM, DIM);
    transpose_ph<<<dim3(FEAT / 32, HEAD_DIM / 32, HEADS), dim3(32, 8)>>>(proj, pt);

    // 1) qkvh = fp16(x @ Wqkv)
    hgemm<false, true><<<dim3((3 * DIM) / BN, ROWS / BM), 256, G_SMEM>>>(
        xh, wqh, nullptr, nullptr, qkvh, ROWS, 3 * DIM, DIM);

    // 2) fused feature + block linear attention
    fused_attn<<<dim3(BATCH * HEADS, SEQ / 128), 256, FS_SMEM>>>(qkvh, pt, ah);

    // 3) out = attn @ Wout + bout
    hgemm<true, false><<<dim3(DIM / BN, ROWS / BM), 256, G_SMEM>>>(
        ah, woh, bout, out, nullptr, ROWS, DIM, DIM);
}

// round 16
// speedup vs baseline: 1.8328x; 1.0863x over previous
#include <cuda_runtime.h>
#include <cuda_fp16.h>
#include <cstdint>
#include <cstddef>

#define DIM      1024
#define HEADS    16
#define HEAD_DIM 64
#define BLK      32
#define FEAT     128
#define BATCH    4
#define SEQ      4096
#define NBLK     (SEQ / BLK)      // 128
#define ROWS     (BATCH * SEQ)    // 16384

// Scratch (allocation-free rule: __device__ globals)
__device__ __half g_qkvh[(size_t)ROWS * 3 * DIM];            // 96 MB fp16
__device__ __half g_xh[(size_t)ROWS * DIM];                  // 32 MB
__device__ __half g_ah[(size_t)ROWS * DIM];                  // 32 MB
__device__ __half g_wqh[(size_t)3 * DIM * DIM];              // 6 MB
__device__ __half g_woh[(size_t)DIM * DIM];                  // 2 MB
__device__ __half g_pt[(size_t)HEADS * FEAT * HEAD_DIM];     // 256 KB projT [h][f][d]

// ---------------------------------------------------------------------------
// helpers
// ---------------------------------------------------------------------------
__device__ __forceinline__ uint32_t smem_u32(const void* p) {
    uint32_t a;
    asm("{ .reg .u64 t; cvta.to.shared.u64 t, %1; cvt.u32.u64 %0, t; }" : "=r"(a) : "l"(p));
    return a;
}

#define SW128(off) ((off) ^ (((off) >> 3) & 0x70))

#define CP16(dst, src) \
    asm volatile("cp.async.cg.shared.global [%0], [%1], 16;" :: "r"(dst), "l"(src) : "memory")
#define CP_COMMIT() asm volatile("cp.async.commit_group;" ::: "memory")
#define CP_WAIT1()  asm volatile("cp.async.wait_group 1;" ::: "memory")
#define CP_WAIT0()  asm volatile("cp.async.wait_group 0;" ::: "memory")

#define LDSM4(r0, r1, r2, r3, addr)                                           \
    asm volatile("ldmatrix.sync.aligned.m8n8.x4.shared.b16 {%0,%1,%2,%3}, [%4];" \
                 : "=r"(r0), "=r"(r1), "=r"(r2), "=r"(r3) : "r"(addr))

#define LDSM4T(r0, r1, r2, r3, addr)                                          \
    asm volatile("ldmatrix.sync.aligned.m8n8.x4.trans.shared.b16 {%0,%1,%2,%3}, [%4];" \
                 : "=r"(r0), "=r"(r1), "=r"(r2), "=r"(r3) : "r"(addr))

#define MMA_F16(d, a0, a1, a2, a3, b0, b1)                                    \
    asm volatile("mma.sync.aligned.m16n8k16.row.col.f32.f16.f16.f32 "         \
                 "{%0,%1,%2,%3}, {%4,%5,%6,%7}, {%8,%9}, {%0,%1,%2,%3};"      \
                 : "+f"((d)[0]), "+f"((d)[1]), "+f"((d)[2]), "+f"((d)[3])     \
                 : "r"(a0), "r"(a1), "r"(a2), "r"(a3), "r"(b0), "r"(b1))

__device__ __forceinline__ float elu1(float x) {
    return (x > 0.0f) ? (x + 1.0f) : __expf(x);
}

// ---------------------------------------------------------------------------
// fp16 mma.sync GEMM (at HMMA dispatch wall, 2 CTAs/SM). OUT16 selects fp16 C.
// ---------------------------------------------------------------------------
#define BM 128
#define BN 128
#define BKH 64
#define NSTAGE 3
#define TILE_B (BM * 128)
#define ST_BYTES (2 * TILE_B)
#define G_SMEM (NSTAGE * ST_BYTES) // 98304 B

template<bool BIAS, bool OUT16>
__global__ __launch_bounds__(256, 2)
void hgemm(const __half* __restrict__ Ah, const __half* __restrict__ Bh,
           const float* __restrict__ bias, float* __restrict__ Cf,
           __half* __restrict__ Ch, int M, int N, int K)
{
    extern __shared__ char smem[];
    const uint32_t sbase = smem_u32(smem);
    const int t = threadIdx.x;
    const int lid = t & 31, wid = t >> 5;
    const int wm = wid & 3, wn = wid >> 2;
    const int m0 = wm * 32, n0 = wn * 64;
    const int bn = blockIdx.x, bm = blockIdx.y;
    const int NK = K / BKH;

    const __half* Ahb = Ah + (size_t)bm * BM * K;
    const __half* Bhb = Bh + (size_t)bn * BN * K;

    const int prow = t >> 3;
    const int pch  = t & 7;

    auto load_stage = [&](int s, int kc) {
        const uint32_t sb0 = sbase + s * ST_BYTES;
        const int koff = kc * BKH;
#pragma unroll
        for (int i = 0; i < 4; i++) {
            int row = prow + i * 32;
            uint32_t off = SW128((uint32_t)(row * 128 + pch * 16));
            size_t g = (size_t)row * K + koff + pch * 8;
            CP16(sb0 + off,          Ahb + g);
            CP16(sb0 + TILE_B + off, Bhb + g);
        }
        CP_COMMIT();
    };

    const int lr = lid & 15;
    const int lk16 = (lid >> 4) * 16;
    const uint32_t aoff = (uint32_t)((m0 + lr) * 128 + lk16);
    uint32_t boff[4];
#pragma unroll
    for (int j = 0; j < 4; j++)
        boff[j] = (uint32_t)((n0 + 16 * j + lr) * 128 + lk16);

    float acc[2][8][4];
#pragma unroll
    for (int mi = 0; mi < 2; mi++)
#pragma unroll
        for (int f = 0; f < 8; f++)
#pragma unroll
            for (int r = 0; r < 4; r++) acc[mi][f][r] = 0.0f;

    load_stage(0, 0);
    load_stage(1, 1);

    for (int it = 0; it < NK; it++) {
        CP_WAIT1();
        __syncthreads();
        const int nxt = it + 2;
        if (nxt < NK) load_stage(nxt % NSTAGE, nxt);

        const uint32_t s0 = sbase + (it % NSTAGE) * ST_BYTES;
        const uint32_t sAh = s0;
        const uint32_t sBh = s0 + TILE_B;

#pragma unroll
        for (int ks = 0; ks < 4; ks++) {
            const uint32_t kb = ks * 32;
            uint32_t ah0[4], ah1[4];
            {
                uint32_t o0 = SW128(aoff + kb);
                uint32_t o1 = SW128(aoff + 16 * 128 + kb);
                LDSM4(ah0[0], ah0[1], ah0[2], ah0[3], sAh + o0);
                LDSM4(ah1[0], ah1[1], ah1[2], ah1[3], sAh + o1);
            }
#pragma unroll
            for (int j = 0; j < 4; j++) {
                uint32_t bh[4];
                uint32_t ob = SW128(boff[j] + kb);
                LDSM4(bh[0], bh[1], bh[2], bh[3], sBh + ob);

                MMA_F16(acc[0][2 * j + 0], ah0[0], ah0[1], ah0[2], ah0[3], bh[0], bh[2]);
                MMA_F16(acc[0][2 * j + 1], ah0[0], ah0[1], ah0[2], ah0[3], bh[1], bh[3]);
                MMA_F16(acc[1][2 * j + 0], ah1[0], ah1[1], ah1[2], ah1[3], bh[0], bh[2]);
                MMA_F16(acc[1][2 * j + 1], ah1[0], ah1[1], ah1[2], ah1[3], bh[1], bh[3]);
            }
        }
    }

    const int g = lid >> 2, tq = lid & 3;
#pragma unroll
    for (int mi = 0; mi < 2; mi++) {
        int rowl = m0 + mi * 16 + g;
#pragma unroll
        for (int f = 0; f < 8; f++) {
            int col = n0 + f * 8 + tq * 2;
            if (OUT16) {
                __half* p0 = Ch + (size_t)(bm * BM + rowl) * N + bn * BN + col;
                __half* p1 = Ch + (size_t)(bm * BM + rowl + 8) * N + bn * BN + col;
                *(__half2*)p0 = __floats2half2_rn(acc[mi][f][0], acc[mi][f][1]);
                *(__half2*)p1 = __floats2half2_rn(acc[mi][f][2], acc[mi][f][3]);
            } else {
                float b0 = 0.0f, b1 = 0.0f;
                if (BIAS) { b0 = bias[bn * BN + col]; b1 = bias[bn * BN + col + 1]; }
                float* p0 = Cf + (size_t)(bm * BM + rowl) * N + bn * BN + col;
                float* p1 = Cf + (size_t)(bm * BM + rowl + 8) * N + bn * BN + col;
                float2 v0 = { acc[mi][f][0] + b0, acc[mi][f][1] + b1 };
                float2 v1 = { acc[mi][f][2] + b0, acc[mi][f][3] + b1 };
                *(float2*)p0 = v0;
                *(float2*)p1 = v1;
            }
        }
    }
}

// ---------------------------------------------------------------------------
// fused_attn: per (b*h, 64-token tile), 2 CTAs/SM:
//   stage q/k (SW128) + proj (SW128) + v (144B rows) via cp.async,
//   feat MMAs -> qf/kf smem (272B rows),
//   2x 32-token blocks: kv = kf^T@v (HMMA), ksum/z fp32, out = qf@kv (HMMA).
// sKV aliases the dead q/k/proj staging region. 77440 B smem.
// ---------------------------------------------------------------------------
#define TOK 64
#define KFB 272
#define VB  144
#define KVB 144
#define FS_Q    0                        // 64 x 128 = 8192
#define FS_K    8192                     // 8192
#define FS_B    16384                    // 16384 (projT 128x64 fp16)
#define FS_KV   0                        // alias (18432 <= 32768 staging)
#define FS_QF   32768                    // 64 x 272 = 17408
#define FS_KF   (FS_QF + TOK * KFB)      // 50176
#define FS_V    (FS_KF + TOK * KFB)      // 67584, 64 x 144 = 9216
#define FS_KSUM (FS_V + TOK * VB)        // 76800, 128 f32
#define FS_Z    (FS_KSUM + 512)          // 77312, 32 f32
#define FS_SMEM (FS_Z + 128)             // 77440

__global__ __launch_bounds__(256, 2)
void fused_attn(const __half* __restrict__ qkvh, const __half* __restrict__ pt,
                __half* __restrict__ attn_h)
{
    extern __shared__ char sm[];
    const uint32_t sb = smem_u32(sm);
    const int t = threadIdx.x;
    const int lid = t & 31, wid = t >> 5;
    const int bh = blockIdx.x, nt = blockIdx.y;
    const int b = bh / HEADS, h = bh - b * HEADS;
    const size_t rowbase = (size_t)b * SEQ + nt * TOK;

    // ---- stage q, k (64x128B SW128), v (64x128B in 144B rows), projT ----
    {
        int r = t >> 2, c2 = (t & 3) * 2;   // rows 0..63, chunks c2, c2+1
        const __half* qrow = qkvh + (rowbase + r) * (3 * DIM) + h * HEAD_DIM;
        const __half* krow = qrow + DIM;
        const __half* vrow = qrow + 2 * DIM;
#pragma unroll
        for (int cc = 0; cc < 2; cc++) {
            int c = c2 + cc;
            uint32_t qk = SW128((uint32_t)(r * 128 + c * 16));
            CP16(sb + FS_Q + qk, qrow + c * 8);
            CP16(sb + FS_K + qk, krow + c * 8);
            CP16(sb + FS_V + (uint32_t)(r * VB + c * 16), vrow + c * 8);
        }
        // projT: 128 rows x 128B
        int pr = t >> 1, ph = t & 1;
        const __half* brow = pt + (size_t)h * FEAT * HEAD_DIM + pr * 64 + ph * 32;
#pragma unroll
        for (int c = 0; c < 4; c++) {
            uint32_t off = SW128((uint32_t)(pr * 128 + ph * 64 + c * 16));
            CP16(sb + FS_B + off, brow + c * 8);
        }
        CP_COMMIT();
    }
    CP_WAIT0();
    __syncthreads();

    // ---- feat: qf/kf = elu([64,64] @ projT^T)+1 -> smem padded rows ----
    {
        const int wm = wid & 1, wn = wid >> 1;     // 2(M) x 4(N)
        const int m0 = wm * 32, n0 = wn * 32;
        const int lr = lid & 15;
        const int lk16 = (lid >> 4) * 16;
        const uint32_t aoff = (uint32_t)((m0 + lr) * 128 + lk16);
        uint32_t boff[2];
#pragma unroll
        for (int j = 0; j < 2; j++)
            boff[j] = (uint32_t)((n0 + 16 * j + lr) * 128 + lk16);
        const int g = lid >> 2, tq = lid & 3;

#pragma unroll
        for (int op = 0; op < 2; op++) {
            const uint32_t sA = sb + (op ? FS_K : FS_Q);
            float acc[2][4][4];
#pragma unroll
            for (int mi = 0; mi < 2; mi++)
#pragma unroll
                for (int f = 0; f < 4; f++)
#pragma unroll
                    for (int r = 0; r < 4; r++) acc[mi][f][r] = 0.0f;

#pragma unroll
            for (int ks = 0; ks < 4; ks++) {
                const uint32_t kb = ks * 32;
                uint32_t a0[4], a1[4];
                LDSM4(a0[0], a0[1], a0[2], a0[3], sA + SW128(aoff + kb));
                LDSM4(a1[0], a1[1], a1[2], a1[3], sA + SW128(aoff + 16 * 128 + kb));
#pragma unroll
                for (int j = 0; j < 2; j++) {
                    uint32_t bfr[4];
                    LDSM4(bfr[0], bfr[1], bfr[2], bfr[3], sb + FS_B + SW128(boff[j] + kb));
                    MMA_F16(acc[0][2 * j + 0], a0[0], a0[1], a0[2], a0[3], bfr[0], bfr[2]);
                    MMA_F16(acc[0][2 * j + 1], a0[0], a0[1], a0[2], a0[3], bfr[1], bfr[3]);
                    MMA_F16(acc[1][2 * j + 0], a1[0], a1[1], a1[2], a1[3], bfr[0], bfr[2]);
                    MMA_F16(acc[1][2 * j + 1], a1[0], a1[1], a1[2], a1[3], bfr[1], bfr[3]);
                }
            }

            char* dst = sm + (op ? FS_KF : FS_QF);
#pragma unroll
            for (int mi = 0; mi < 2; mi++) {
                int rowl = m0 + mi * 16 + g;
#pragma unroll
                for (int f = 0; f < 4; f++) {
                    int col = n0 + f * 8 + tq * 2;
                    *(__half2*)(dst + rowl * KFB + col * 2) =
                        __floats2half2_rn(elu1(acc[mi][f][0]), elu1(acc[mi][f][1]));
                    *(__half2*)(dst + (rowl + 8) * KFB + col * 2) =
                        __floats2half2_rn(elu1(acc[mi][f][2]), elu1(acc[mi][f][3]));
                }
            }
        }
    }
    __syncthreads();   // qf/kf visible; q/k/proj staging dead -> sKV alias safe

    // ---- per 32-token block: kv (HMMA), ksum/z (fp32), out (HMMA) ----
    const int f0 = wid * 16;
    const int trow = (lid & 7) + ((lid >> 4) & 1) * 8;
    const int tcol8 = ((lid >> 3) & 1) * 8;
    const int wm2 = wid & 1, wn2 = wid >> 1;
    const int s0 = wm2 * 16, d0 = wn2 * 16;
    const int g = lid >> 2, tq = lid & 3;

    for (int m2 = 0; m2 < 2; m2++) {
        const int sr = m2 * 32;

        // ksum (t<128) + MMA1 accumulate (regs only)
        float ks_acc = 0.0f;
        if (t < FEAT) {
            for (int s = 0; s < BLK; s++)
                ks_acc += __half2float(*(const __half*)(sm + FS_KF + (sr + s) * KFB + t * 2));
        }
        float acc1[8][4];
#pragma unroll
        for (int j = 0; j < 8; j++)
#pragma unroll
            for (int r = 0; r < 4; r++) acc1[j][r] = 0.0f;

#pragma unroll
        for (int ksi = 0; ksi < 2; ksi++) {
            uint32_t a[4];
            LDSM4T(a[0], a[1], a[2], a[3],
                   sb + FS_KF + (uint32_t)((sr + trow + ksi * 16) * KFB + (f0 + tcol8) * 2));
#pragma unroll
            for (int nj = 0; nj < 4; nj++) {
                uint32_t bf[4];
                LDSM4T(bf[0], bf[1], bf[2], bf[3],
                       sb + FS_V + (uint32_t)((sr + trow + ksi * 16) * VB + (nj * 16 + tcol8) * 2));
                MMA_F16(acc1[2 * nj + 0], a[0], a[1], a[2], a[3], bf[0], bf[2]);
                MMA_F16(acc1[2 * nj + 1], a[0], a[1], a[2], a[3], bf[1], bf[3]);
            }
        }

        // write kv + ksum
        if (t < FEAT) *(float*)(sm + FS_KSUM + t * 4) = ks_acc;
#pragma unroll
        for (int j = 0; j < 8; j++) {
            int dd = j * 8 + tq * 2;
            *(__half2*)(sm + FS_KV + (f0 + g) * KVB + dd * 2) =
                __floats2half2_rn(acc1[j][0], acc1[j][1]);
            *(__half2*)(sm + FS_KV + (f0 + g + 8) * KVB + dd * 2) =
                __floats2half2_rn(acc1[j][2], acc1[j][3]);
        }
        __syncthreads();

        // z (t<32) + MMA2
        if (t < BLK) {
            float za = 0.0f;
            for (int f = 0; f < FEAT; f++)
                za += __half2float(*(const __half*)(sm + FS_QF + (sr + t) * KFB + f * 2))
                    * *(const float*)(sm + FS_KSUM + f * 4);
            *(float*)(sm + FS_Z + t * 4) = 1.0f / (za + 1e-8f);
        }
        float acc2[2][4];
#pragma unroll
        for (int j = 0; j < 2; j++)
#pragma unroll
            for (int r = 0; r < 4; r++) acc2[j][r] = 0.0f;

        const uint32_t qoff = (uint32_t)(FS_QF + (sr + s0 + (lid & 15)) * KFB + (lid >> 4) * 16);
#pragma unroll
        for (int ksi = 0; ksi < 8; ksi++) {
            uint32_t a[4];
            LDSM4(a[0], a[1], a[2], a[3], sb + qoff + ksi * 32);
            uint32_t bf[4];
            LDSM4T(bf[0], bf[1], bf[2], bf[3],
                   sb + FS_KV + (uint32_t)((ksi * 16 + trow) * KVB + (d0 + tcol8) * 2));
            MMA_F16(acc2[0], a[0], a[1], a[2], a[3], bf[0], bf[2]);
            MMA_F16(acc2[1], a[0], a[1], a[2], a[3], bf[1], bf[3]);
        }
        __syncthreads();

        // epilogue: scale by z, write fp16 attn
#pragma unroll
        for (int half = 0; half < 2; half++) {
            int s = s0 + g + half * 8;
            float z = *(const float*)(sm + FS_Z + s * 4);
            size_t off = (rowbase + sr + s) * DIM + h * HEAD_DIM;
            *(__half2*)(attn_h + off + d0 + tq * 2) =
                __floats2half2_rn(acc2[0][2 * half] * z, acc2[0][2 * half + 1] * z);
            *(__half2*)(attn_h + off + d0 + 8 + tq * 2) =
                __floats2half2_rn(acc2[1][2 * half] * z, acc2[1][2 * half + 1] * z);
        }
    }
}

// ---------------------------------------------------------------------------
// prep kernels
// ---------------------------------------------------------------------------
__global__ void round_kernel(const float* __restrict__ in, __half* __restrict__ h,
                             int n4)
{
    int i = blockIdx.x * blockDim.x + threadIdx.x;
    if (i >= n4) return;
    float4 v = ((const float4*)in)[i];
    ((__half2*)h)[2 * i]     = __halves2half2(__float2half_rn(v.x), __float2half_rn(v.y));
    ((__half2*)h)[2 * i + 1] = __halves2half2(__float2half_rn(v.z), __float2half_rn(v.w));
}

__global__ void transpose_h(const float* __restrict__ in,
                            __half* __restrict__ oh, int R, int C)
{
    __shared__ float tile[32][33];
    int bx = blockIdx.x * 32, by = blockIdx.y * 32;
#pragma unroll
    for (int i = 0; i < 32; i += 8)
        tile[threadIdx.y + i][threadIdx.x] =
            in[(size_t)(by + threadIdx.y + i) * C + bx + threadIdx.x];
    __syncthreads();
#pragma unroll
    for (int i = 0; i < 32; i += 8) {
        size_t idx = (size_t)(bx + threadIdx.y + i) * R + by + threadIdx.x;
        oh[idx] = __float2half_rn(tile[threadIdx.x][threadIdx.y + i]);
    }
}

__global__ void transpose_ph(const float* __restrict__ in, __half* __restrict__ out)
{
    __shared__ float tile[32][33];
    int hh = blockIdx.z;
    int bx = blockIdx.x * 32;
    int by = blockIdx.y * 32;
    const float* src = in + (size_t)hh * HEAD_DIM * FEAT;
    __half* dst = out + (size_t)hh * FEAT * HEAD_DIM;
#pragma unroll
    for (int i = 0; i < 32; i += 8)
        tile[threadIdx.y + i][threadIdx.x] =
            src[(size_t)(by + threadIdx.y + i) * FEAT + bx + threadIdx.x];
    __syncthreads();
#pragma unroll
    for (int i = 0; i < 32; i += 8)
        dst[(size_t)(bx + threadIdx.y + i) * HEAD_DIM + by + threadIdx.x] =
            __float2half_rn(tile[threadIdx.x][threadIdx.y + i]);
}

// ---------------------------------------------------------------------------
extern "C" void kernel_launch(void* const* d_in, const int* in_sizes, int n_in,
                              void* d_out, int out_size)
{
    const float* x    = (const float*)d_in[0];
    const float* Wqkv = (const float*)d_in[1];
    const float* proj = (const float*)d_in[2];
    const float* Wout = (const float*)d_in[3];
    const float* bout = (const float*)d_in[4];
    float* out = (float*)d_out;

    __half *qkvh, *xh, *ah, *wqh, *woh, *pt;
    cudaGetSymbolAddress((void**)&qkvh, g_qkvh);
    cudaGetSymbolAddress((void**)&xh,   g_xh);
    cudaGetSymbolAddress((void**)&ah,   g_ah);
    cudaGetSymbolAddress((void**)&wqh,  g_wqh);
    cudaGetSymbolAddress((void**)&woh,  g_woh);
    cudaGetSymbolAddress((void**)&pt,   g_pt);

    cudaFuncSetAttribute((const void*)hgemm<false, true>,
                         cudaFuncAttributeMaxDynamicSharedMemorySize, G_SMEM);
    cudaFuncSetAttribute((const void*)hgemm<true, false>,
                         cudaFuncAttributeMaxDynamicSharedMemorySize, G_SMEM);
    cudaFuncSetAttribute((const void*)fused_attn,
                         cudaFuncAttributeMaxDynamicSharedMemorySize, FS_SMEM);

    // 0) operand prep
    {
        int n4 = ROWS * DIM / 4;
        round_kernel<<<(n4 + 255) / 256, 256>>>(x, xh, n4);
    }
    transpose_h<<<dim3((3 * DIM) / 32, DIM / 32), dim3(32, 8)>>>(Wqkv, wqh, DIM, 3 * DIM);
    transpose_h<<<dim3(DIM / 32, DIM / 32), dim3(32, 8)>>>(Wout, woh, DIM, DIM);
    transpose_ph<<<dim3(FEAT / 32, HEAD_DIM / 32, HEADS), dim3(32, 8)>>>(proj, pt);

    // 1) qkvh = fp16(x @ Wqkv)
    hgemm<false, true><<<dim3((3 * DIM) / BN, ROWS / BM), 256, G_SMEM>>>(
        xh, wqh, nullptr, nullptr, qkvh, ROWS, 3 * DIM, DIM);

    // 2) fused feature + block linear attention (64-token tiles, 2 CTAs/SM)
    fused_attn<<<dim3(BATCH * HEADS, SEQ / TOK), 256, FS_SMEM>>>(qkvh, pt, ah);

    // 3) out = attn @ Wout + bout
    hgemm<true, false><<<dim3(DIM / BN, ROWS / BM), 256, G_SMEM>>>(
        ah, woh, bout, out, nullptr, ROWS, DIM, DIM);
}